// round 8
// baseline (speedup 1.0000x reference)
#include <cuda_runtime.h>

#define NI   6001
#define DD   64
#define LL   200
#define BB   32
#define NP   (BB*LL)   // 6400 positions
#define QT   32
#define KT   32
#define CAPH 128       // max nonzeros per HALF adj row

// ---- device scratch (no allocations allowed) ----
__device__ float g_h[NI*DD];
__device__ float g_wh1[NI];
__device__ float g_wh2[NI];
__device__ float g_trans[NI*DD];
__device__ float g_gat[NI*DD];
__device__ float g_seqs[NP*DD];
__device__ float g_M1[NP*DD];
__device__ float g_M2[NP*DD];
__device__ float g_score[BB*LL*LL];

__device__ __forceinline__ float tanha(float x) {
    float t;
    asm("tanh.approx.f32 %0, %1;" : "=f"(t) : "f"(x));
    return t;
}

// ---- 4x4-tile GEMM helper ----
__device__ __forceinline__ void gemm_acc(const float* __restrict__ A,
                                         const float* __restrict__ B,
                                         float acc[4][4], int r0, int c0) {
#pragma unroll 4
    for (int k4 = 0; k4 < 64; k4 += 4) {
        float aa[4][4], bb[4][4];
#pragma unroll
        for (int i = 0; i < 4; i++)
            *(float4*)aa[i] = *(const float4*)(A + (r0+i)*64 + k4);
#pragma unroll
        for (int kk = 0; kk < 4; kk++)
            *(float4*)bb[kk] = *(const float4*)(B + (k4+kk)*64 + c0);
#pragma unroll
        for (int kk = 0; kk < 4; kk++)
#pragma unroll
            for (int i = 0; i < 4; i++)
#pragma unroll
                for (int j = 0; j < 4; j++)
                    acc[i][j] = fmaf(aa[i][kk], bb[kk][j], acc[i][j]);
    }
}

// ---- 2x4-tile GEMM helpers ----
__device__ __forceinline__ void g24(const float* __restrict__ A,
                                    const float* __restrict__ B,
                                    float acc[2][4], int r0, int c0) {
#pragma unroll 4
    for (int k4 = 0; k4 < 64; k4 += 4) {
        float aa[2][4], bb[4][4];
#pragma unroll
        for (int i = 0; i < 2; i++)
            *(float4*)aa[i] = *(const float4*)(A + (r0+i)*64 + k4);
#pragma unroll
        for (int kk = 0; kk < 4; kk++)
            *(float4*)bb[kk] = *(const float4*)(B + (k4+kk)*64 + c0);
#pragma unroll
        for (int kk = 0; kk < 4; kk++)
#pragma unroll
            for (int i = 0; i < 2; i++)
#pragma unroll
                for (int j = 0; j < 4; j++)
                    acc[i][j] = fmaf(aa[i][kk], bb[kk][j], acc[i][j]);
    }
}

__device__ __forceinline__ void g24_2B(const float* __restrict__ A,
                                       const float* __restrict__ B1,
                                       const float* __restrict__ B2,
                                       float accP[2][4], float accQ[2][4],
                                       int r0, int c0) {
#pragma unroll 4
    for (int k4 = 0; k4 < 64; k4 += 4) {
        float aa[2][4], b1[4][4], b2[4][4];
#pragma unroll
        for (int i = 0; i < 2; i++)
            *(float4*)aa[i] = *(const float4*)(A + (r0+i)*64 + k4);
#pragma unroll
        for (int kk = 0; kk < 4; kk++) {
            *(float4*)b1[kk] = *(const float4*)(B1 + (k4+kk)*64 + c0);
            *(float4*)b2[kk] = *(const float4*)(B2 + (k4+kk)*64 + c0);
        }
#pragma unroll
        for (int kk = 0; kk < 4; kk++)
#pragma unroll
            for (int i = 0; i < 2; i++)
#pragma unroll
                for (int j = 0; j < 4; j++) {
                    accP[i][j] = fmaf(aa[i][kk], b1[kk][j], accP[i][j]);
                    accQ[i][j] = fmaf(aa[i][kk], b2[kk][j], accQ[i][j]);
                }
    }
}

__device__ __forceinline__ void g24_2A(const float* __restrict__ A1,
                                       const float* __restrict__ A2,
                                       const float* __restrict__ B1,
                                       const float* __restrict__ B2,
                                       float acc[2][4], int r0, int c0) {
#pragma unroll 4
    for (int k4 = 0; k4 < 64; k4 += 4) {
        float a1[2][4], a2[2][4], b1[4][4], b2[4][4];
#pragma unroll
        for (int i = 0; i < 2; i++) {
            *(float4*)a1[i] = *(const float4*)(A1 + (r0+i)*64 + k4);
            *(float4*)a2[i] = *(const float4*)(A2 + (r0+i)*64 + k4);
        }
#pragma unroll
        for (int kk = 0; kk < 4; kk++) {
            *(float4*)b1[kk] = *(const float4*)(B1 + (k4+kk)*64 + c0);
            *(float4*)b2[kk] = *(const float4*)(B2 + (k4+kk)*64 + c0);
        }
#pragma unroll
        for (int kk = 0; kk < 4; kk++)
#pragma unroll
            for (int i = 0; i < 2; i++)
#pragma unroll
                for (int j = 0; j < 4; j++) {
                    acc[i][j] = fmaf(a1[i][kk], b1[kk][j], acc[i][j]);
                    acc[i][j] = fmaf(a2[i][kk], b2[kk][j], acc[i][j]);
                }
    }
}

// ============================================================
// K1: tiled  h = emb@W ; wh1/wh2 fused.  grid ceil(NI/64)
// ============================================================
__global__ __launch_bounds__(256) void k_h2(const float* __restrict__ emb,
                                            const float* __restrict__ W,
                                            const float* __restrict__ a) {
    __shared__ float Xs[64*64];
    __shared__ float Ws[64*64];
    int t = threadIdx.x;
    int base = blockIdx.x * 64;
    for (int i = t; i < 1024; i += 256) {
        int row = i >> 4, c4 = (i & 15) * 4;
        float4 v = make_float4(0.f,0.f,0.f,0.f);
        if (base + row < NI) v = *(const float4*)(emb + (base+row)*64 + c4);
        *(float4*)(Xs + row*64 + c4) = v;
        *(float4*)(Ws + i*4) = *(const float4*)(W + i*4);
    }
    __syncthreads();
    int tx = t & 15, ty = t >> 4;
    int r0 = ty*4, c0 = tx*4;
    float acc[4][4] = {};
    gemm_acc(Xs, Ws, acc, r0, c0);

    float4 a1v = *(const float4*)(a + c0);
    float4 a2v = *(const float4*)(a + 64 + c0);
#pragma unroll
    for (int i = 0; i < 4; i++) {
        int gr = base + r0 + i;
        if (gr < NI)
            *(float4*)(g_h + gr*64 + c0) =
                make_float4(acc[i][0], acc[i][1], acc[i][2], acc[i][3]);
        float p1 = acc[i][0]*a1v.x + acc[i][1]*a1v.y + acc[i][2]*a1v.z + acc[i][3]*a1v.w;
        float p2 = acc[i][0]*a2v.x + acc[i][1]*a2v.y + acc[i][2]*a2v.z + acc[i][3]*a2v.w;
#pragma unroll
        for (int o = 8; o > 0; o >>= 1) {
            p1 += __shfl_xor_sync(0xffffffffu, p1, o);
            p2 += __shfl_xor_sync(0xffffffffu, p2, o);
        }
        if (tx == 0 && gr < NI) { g_wh1[gr] = p1; g_wh2[gr] = p2; }
    }
}

// ============================================================
// K2: warp-PAIR per row. Each warp streams+compacts half the row,
// applies its own list, then the pair merges partials via smem.
// Block 256 = 8 warps = 4 rows. grid ceil(NI/4).
// ============================================================
__device__ __forceinline__ int emit4(float4 v, int colbase, int cnt,
                                     int* cols, float* vals,
                                     int lane, unsigned lt) {
    unsigned mx = __ballot_sync(0xffffffffu, v.x != 0.f);
    unsigned my = __ballot_sync(0xffffffffu, v.y != 0.f);
    unsigned mz = __ballot_sync(0xffffffffu, v.z != 0.f);
    unsigned mw = __ballot_sync(0xffffffffu, v.w != 0.f);
    if ((mx | my | mz | mw) == 0u) return cnt;
    int cx = __popc(mx), cy = __popc(my), cz = __popc(mz), cw = __popc(mw);
    int col = colbase + lane*4;
    if (v.x != 0.f) {
        int w = cnt + __popc(mx & lt);
        if (w < CAPH) { cols[w] = col;     vals[w] = v.x; }
    }
    if (v.y != 0.f) {
        int w = cnt + cx + __popc(my & lt);
        if (w < CAPH) { cols[w] = col + 1; vals[w] = v.y; }
    }
    if (v.z != 0.f) {
        int w = cnt + cx + cy + __popc(mz & lt);
        if (w < CAPH) { cols[w] = col + 2; vals[w] = v.z; }
    }
    if (v.w != 0.f) {
        int w = cnt + cx + cy + cz + __popc(mw & lt);
        if (w < CAPH) { cols[w] = col + 3; vals[w] = v.w; }
    }
    return cnt + cx + cy + cz + cw;
}

__device__ __forceinline__ void apply_one(int j, float av, int lane, float w1,
                                          float& t0, float& t1,
                                          float& g0, float& g1, float& den) {
    float hj0 = g_h[j*DD + lane];
    float hj1 = g_h[j*DD + 32 + lane];
    float e = w1 + g_wh2[j];
    e = (e > 0.f) ? e : 0.01f * e;
    float w = __expf(e);
    t0 = fmaf(av, hj0, t0);
    t1 = fmaf(av, hj1, t1);
    g0 = fmaf(w, hj0, g0);
    g1 = fmaf(w, hj1, g1);
    den += w;
}

__global__ __launch_bounds__(256) void k_adjf(const float* __restrict__ adj) {
    __shared__ int   scols[8*CAPH];
    __shared__ float svals[8*CAPH];
    __shared__ float sh0[8][32], sh1[8][32], sh2[8][32], sh3[8][32];
    __shared__ float shd[8];

    int warp = threadIdx.x >> 5;
    int lane = threadIdx.x & 31;
    int rloc = warp >> 1;
    int half = warp & 1;
    int row  = blockIdx.x * 4 + rloc;
    if (row >= NI) row = NI - 1;       // clamp: duplicates write identical data

    unsigned lt = (1u << lane) - 1u;
    int*   cols = scols + warp*CAPH;
    float* vals = svals + warp*CAPH;
    const float* arow = adj + (long long)row * NI;
    int cnt = 0;

    int p0 = (4 - (row & 3)) & 3;
    const float4* a4 = (const float4*)(arow + p0);
    int n4 = (NI - p0) >> 2;
    int h0 = n4 >> 1;                  // warp0: [0,h0), warp1: [h0,n4)+tail

    int beg, end;
    if (half == 0) {
        // peel to 16B alignment
        float a = (lane < p0) ? arow[lane] : 0.f;
        unsigned m = __ballot_sync(0xffffffffu, a != 0.f);
        if (a != 0.f) {
            int off = __popc(m & lt);
            if (cnt + off < CAPH) { cols[cnt+off] = lane; vals[cnt+off] = a; }
        }
        cnt += __popc(m);
        beg = 0; end = h0;
    } else {
        beg = h0; end = n4;
    }

    int i = beg;
    for (; i + 128 <= end; i += 128) {
        float4 v0 = __ldcs(&a4[i       + lane]);
        float4 v1 = __ldcs(&a4[i +  32 + lane]);
        float4 v2 = __ldcs(&a4[i +  64 + lane]);
        float4 v3 = __ldcs(&a4[i +  96 + lane]);
        cnt = emit4(v0, p0 + (i      )*4, cnt, cols, vals, lane, lt);
        cnt = emit4(v1, p0 + (i +  32)*4, cnt, cols, vals, lane, lt);
        cnt = emit4(v2, p0 + (i +  64)*4, cnt, cols, vals, lane, lt);
        cnt = emit4(v3, p0 + (i +  96)*4, cnt, cols, vals, lane, lt);
    }
    for (; i < end; i += 32) {
        float4 v = (i + lane < end) ? __ldcs(&a4[i + lane])
                                    : make_float4(0.f,0.f,0.f,0.f);
        cnt = emit4(v, p0 + i*4, cnt, cols, vals, lane, lt);
    }
    if (half == 1) {
        int st = p0 + n4*4;
        int j = st + lane;
        float a = (j < NI) ? arow[j] : 0.f;
        unsigned m = __ballot_sync(0xffffffffu, a != 0.f);
        if (a != 0.f) {
            int off = __popc(m & lt);
            if (cnt + off < CAPH) { cols[cnt+off] = j; vals[cnt+off] = a; }
        }
        cnt += __popc(m);
    }
    int n = (cnt < CAPH) ? cnt : CAPH;

    // --- phase 2: gather + apply own list (8-deep unroll) ---
    float w1 = g_wh1[row];
    float t0 = 0.f, t1 = 0.f, g0 = 0.f, g1 = 0.f, den = 0.f;
    int k = 0;
    for (; k + 8 <= n; k += 8) {
        int   j0 = cols[k],   j1 = cols[k+1], j2 = cols[k+2], j3 = cols[k+3];
        int   j4 = cols[k+4], j5 = cols[k+5], j6 = cols[k+6], j7 = cols[k+7];
        float a0 = vals[k],   a1 = vals[k+1], a2 = vals[k+2], a3 = vals[k+3];
        float a4v = vals[k+4], a5 = vals[k+5], a6 = vals[k+6], a7 = vals[k+7];
        apply_one(j0, a0, lane, w1, t0, t1, g0, g1, den);
        apply_one(j1, a1, lane, w1, t0, t1, g0, g1, den);
        apply_one(j2, a2, lane, w1, t0, t1, g0, g1, den);
        apply_one(j3, a3, lane, w1, t0, t1, g0, g1, den);
        apply_one(j4, a4v, lane, w1, t0, t1, g0, g1, den);
        apply_one(j5, a5, lane, w1, t0, t1, g0, g1, den);
        apply_one(j6, a6, lane, w1, t0, t1, g0, g1, den);
        apply_one(j7, a7, lane, w1, t0, t1, g0, g1, den);
    }
    for (; k < n; k++) apply_one(cols[k], vals[k], lane, w1, t0, t1, g0, g1, den);

    // --- merge warp pair ---
    sh0[warp][lane] = t0;
    sh1[warp][lane] = t1;
    sh2[warp][lane] = g0;
    sh3[warp][lane] = g1;
    if (lane == 0) shd[warp] = den;
    __syncthreads();

    if (half == 0) {
        t0  += sh0[warp+1][lane];
        t1  += sh1[warp+1][lane];
        g0  += sh2[warp+1][lane];
        g1  += sh3[warp+1][lane];
        den += shd[warp+1];
        float inv = 1.f / den;
        g_trans[row*DD + lane]      = t0;
        g_trans[row*DD + 32 + lane] = t1;
        g_gat[row*DD + lane]        = g0 * inv;
        g_gat[row*DD + 32 + lane]   = g1 * inv;
    }
}

// ============================================================
// K3: tiled seq — 32 positions/block, 48KB dyn smem, grid 200.
// ============================================================
__global__ __launch_bounds__(256) void k_seq2(const int* __restrict__ logs,
                                              const float* __restrict__ emb,
                                              const float* __restrict__ posT,
                                              const float* __restrict__ cc,
                                              const float* __restrict__ cn,
                                              const float* __restrict__ W1,
                                              const float* __restrict__ W2) {
    extern __shared__ float sm[];
    float* GR = sm;
    float* TR = sm + 2048;
    float* WA = sm + 4096;
    float* WB = sm + 8192;
    __shared__ int ids[32];

    int t = threadIdx.x;
    int p0 = blockIdx.x * 32;
    if (t < 32) ids[t] = logs[p0 + t];
    for (int i = t; i < 1024; i += 256) {
        *(float4*)(WA + i*4) = *(const float4*)(cc + i*4);
        *(float4*)(WB + i*4) = *(const float4*)(cn + i*4);
    }
    __syncthreads();
    for (int i = t; i < 512; i += 256) {
        int row = i >> 4, c4 = (i & 15) * 4;
        int id = ids[row];
        *(float4*)(GR + row*64 + c4) = *(const float4*)(g_gat + id*64 + c4);
        *(float4*)(TR + row*64 + c4) = *(const float4*)(g_trans + id*64 + c4);
    }
    __syncthreads();

    int tx = t & 15, ty = t >> 4;
    int r0 = ty*2, c0 = tx*4;
    float acc[2][4] = {};
    g24_2A(GR, TR, WA, WB, acc, r0, c0);
    __syncthreads();

    for (int i = t; i < 1024; i += 256) {
        *(float4*)(WA + i*4) = *(const float4*)(W1 + i*4);
        *(float4*)(WB + i*4) = *(const float4*)(W2 + i*4);
    }
#pragma unroll
    for (int i = 0; i < 2; i++) {
        int r = r0 + i;
        int id = ids[r];
        int p  = p0 + r;
        int l  = p % LL;
        float4 gv = *(float4*)(GR + r*64 + c0);
        float4 tv = *(float4*)(TR + r*64 + c0);
        float4 ev = *(const float4*)(emb + id*64 + c0);
        float4 pv = make_float4(0.f,0.f,0.f,0.f);
        if (id != 0) pv = *(const float4*)(posT + l*64 + c0);
        float s0 = tv.x + ev.x, s1 = tv.y + ev.y, s2 = tv.z + ev.z, s3 = tv.w + ev.w;
        float c0f = __fdividef(1.f, 1.f + __expf(-acc[i][0]));
        float c1f = __fdividef(1.f, 1.f + __expf(-acc[i][1]));
        float c2f = __fdividef(1.f, 1.f + __expf(-acc[i][2]));
        float c3f = __fdividef(1.f, 1.f + __expf(-acc[i][3]));
        s0 = fmaf(c0f, gv.x - tv.x, s0);
        s1 = fmaf(c1f, gv.y - tv.y, s1);
        s2 = fmaf(c2f, gv.z - tv.z, s2);
        s3 = fmaf(c3f, gv.w - tv.w, s3);
        *(float4*)(g_seqs + p*64 + c0) = make_float4(s0, s1, s2, s3);
        *(float4*)(GR + r*64 + c0) =
            make_float4(s0 + pv.x, s1 + pv.y, s2 + pv.z, s3 + pv.w);
    }
    __syncthreads();

    float m1[2][4] = {}, m2[2][4] = {};
    g24_2B(GR, WA, WB, m1, m2, r0, c0);
#pragma unroll
    for (int i = 0; i < 2; i++) {
        int p = p0 + r0 + i;
        *(float4*)(g_M1 + p*64 + c0) =
            make_float4(0.5f*m1[i][0], 0.5f*m1[i][1], 0.5f*m1[i][2], 0.5f*m1[i][3]);
        *(float4*)(g_M2 + p*64 + c0) =
            make_float4(0.5f*m2[i][0], 0.5f*m2[i][1], 0.5f*m2[i][2], 0.5f*m2[i][3]);
    }
}

// ============================================================
// K4a: score tiles — one block per causal 32x32 tile.
// ============================================================
__global__ __launch_bounds__(256) void k_score(const float* __restrict__ battn) {
    int b   = blockIdx.y;
    int tid = blockIdx.x;
    int qt = 0, base = 0;
    while (base + qt + 1 <= tid) { base += qt + 1; qt++; }
    int kt = tid - base;
    int t = threadIdx.x;

    __shared__ float m1s[32*68];
    __shared__ float m2s[32*64];
    __shared__ float bs2[64];

    for (int i = t; i < 512; i += 256) {
        int row = i >> 4, c4 = (i & 15)*4;
        int qg = qt*QT + row;
        float4 v = (qg < LL) ? *(const float4*)(g_M1 + (b*LL+qg)*64 + c4)
                             : make_float4(0.f,0.f,0.f,0.f);
        *(float4*)(m1s + row*68 + c4) = v;
        int kg = kt*KT + row;
        float4 w = (kg < LL) ? *(const float4*)(g_M2 + (b*LL+kg)*64 + c4)
                             : make_float4(0.f,0.f,0.f,0.f);
        *(float4*)(m2s + row*64 + c4) = w;
    }
    if (t < 64) bs2[t] = 0.5f * battn[t];
    __syncthreads();

    int ql = t & 31;
    int kb = (t >> 5) << 2;
    int qg = qt*QT + ql;

    float hs = 0.f;
#pragma unroll
    for (int d = 0; d < 64; d += 4) {
        float4 bv = *(float4*)(bs2 + d);
        hs += bv.x + bv.y + bv.z + bv.w;
    }

    float s0 = 0.f, s1 = 0.f, s2 = 0.f, s3 = 0.f;
#pragma unroll 4
    for (int d4 = 0; d4 < 64; d4 += 4) {
        float4 m1v = *(float4*)(m1s + ql*68 + d4);
        float4 b2  = *(float4*)(bs2 + d4);
        float4 k0  = *(float4*)(m2s + (kb+0)*64 + d4);
        float4 k1  = *(float4*)(m2s + (kb+1)*64 + d4);
        float4 k2  = *(float4*)(m2s + (kb+2)*64 + d4);
        float4 k3  = *(float4*)(m2s + (kb+3)*64 + d4);
        s0 = fmaf(b2.x, tanha(m1v.x + k0.x), s0);
        s1 = fmaf(b2.x, tanha(m1v.x + k1.x), s1);
        s2 = fmaf(b2.x, tanha(m1v.x + k2.x), s2);
        s3 = fmaf(b2.x, tanha(m1v.x + k3.x), s3);
        s0 = fmaf(b2.y, tanha(m1v.y + k0.y), s0);
        s1 = fmaf(b2.y, tanha(m1v.y + k1.y), s1);
        s2 = fmaf(b2.y, tanha(m1v.y + k2.y), s2);
        s3 = fmaf(b2.y, tanha(m1v.y + k3.y), s3);
        s0 = fmaf(b2.z, tanha(m1v.z + k0.z), s0);
        s1 = fmaf(b2.z, tanha(m1v.z + k1.z), s1);
        s2 = fmaf(b2.z, tanha(m1v.z + k2.z), s2);
        s3 = fmaf(b2.z, tanha(m1v.z + k3.z), s3);
        s0 = fmaf(b2.w, tanha(m1v.w + k0.w), s0);
        s1 = fmaf(b2.w, tanha(m1v.w + k1.w), s1);
        s2 = fmaf(b2.w, tanha(m1v.w + k2.w), s2);
        s3 = fmaf(b2.w, tanha(m1v.w + k3.w), s3);
    }
    if (qg < LL) {
        int kg0 = kt*KT + kb;
        float* srow = &g_score[((long long)b*LL + qg)*LL];
        if (kg0+0 < LL) srow[kg0+0] = (kg0+0 <= qg) ? s0 + hs : 0.f;
        if (kg0+1 < LL) srow[kg0+1] = (kg0+1 <= qg) ? s1 + hs : 0.f;
        if (kg0+2 < LL) srow[kg0+2] = (kg0+2 <= qg) ? s2 + hs : 0.f;
        if (kg0+3 < LL) srow[kg0+3] = (kg0+3 <= qg) ? s3 + hs : 0.f;
    }
}

// ============================================================
// K5 (fused): phase A  F0 = score @ seqs ; then FFN + UpDown + logits.
// ============================================================
__global__ __launch_bounds__(256) void k_ffn3(const int* __restrict__ pos_s,
                                              const int* __restrict__ neg_s,
                                              const float* __restrict__ emb,
                                              const float* __restrict__ c1w,
                                              const float* __restrict__ c1b,
                                              const float* __restrict__ c2w,
                                              const float* __restrict__ c2b,
                                              const float* __restrict__ upw,
                                              const float* __restrict__ upb,
                                              const float* __restrict__ gw,
                                              const float* __restrict__ gb,
                                              const float* __restrict__ dw,
                                              const float* __restrict__ db,
                                              float* __restrict__ out) {
    extern __shared__ float sm[];
    float* F0 = sm;
    float* R1 = sm + 2048;
    float* F2 = sm + 4096;
    float* WA = sm + 6144;
    float* WB = sm + 10240;
    float* GU = sm;
    float* seqss = WA;
    float* scs   = WB;

    int t = threadIdx.x;
    int b  = blockIdx.y;
    int qt = (int)gridDim.x - 1 - (int)blockIdx.x;
    int tx = t & 15, ty = t >> 4;
    int r0 = ty*2, c0 = tx*4;

    // ---- phase A: F0 = score @ seqs ----
    int qb = t >> 3;
    int dbase = (t & 7) << 3;
    float acc[8];
#pragma unroll
    for (int i = 0; i < 8; i++) acc[i] = 0.f;

    for (int kt = 0; kt <= qt; kt++) {
        __syncthreads();
        for (int i = t; i < 512; i += 256) {
            int kl = i >> 4, c4 = (i & 15) * 4;
            int kg = kt*KT + kl;
            float4 v = (kg < LL) ? *(const float4*)(g_seqs + (b*LL+kg)*64 + c4)
                                 : make_float4(0.f,0.f,0.f,0.f);
            *(float4*)(seqss + kl*64 + c4) = v;
        }
        {
            int ql = t >> 3, c4 = (t & 7) * 4;
            int qg = qt*QT + ql, kg = kt*KT + c4;
            float4 v = (qg < LL && kg < LL)
                     ? *(const float4*)(g_score + ((long long)b*LL + qg)*LL + kg)
                     : make_float4(0.f,0.f,0.f,0.f);
            *(float4*)(scs + ql*36 + c4) = v;
        }
        __syncthreads();
#pragma unroll 4
        for (int k = 0; k < KT; k++) {
            float sv = scs[qb*36 + k];
            float4 v0 = *(float4*)(seqss + k*64 + dbase);
            float4 v1 = *(float4*)(seqss + k*64 + dbase + 4);
            acc[0] = fmaf(sv, v0.x, acc[0]);
            acc[1] = fmaf(sv, v0.y, acc[1]);
            acc[2] = fmaf(sv, v0.z, acc[2]);
            acc[3] = fmaf(sv, v0.w, acc[3]);
            acc[4] = fmaf(sv, v1.x, acc[4]);
            acc[5] = fmaf(sv, v1.y, acc[5]);
            acc[6] = fmaf(sv, v1.z, acc[6]);
            acc[7] = fmaf(sv, v1.w, acc[7]);
        }
    }
    __syncthreads();
    *(float4*)(F0 + qb*64 + dbase)     = make_float4(acc[0], acc[1], acc[2], acc[3]);
    *(float4*)(F0 + qb*64 + dbase + 4) = make_float4(acc[4], acc[5], acc[6], acc[7]);
    __syncthreads();

    // ---- FFN path ----
    for (int i = t; i < 1024; i += 256) {
        *(float4*)(WA + i*4) = *(const float4*)(c1w + i*4);
        *(float4*)(WB + i*4) = *(const float4*)(c2w + i*4);
    }
    __syncthreads();

    {
        float a2[2][4] = {};
        g24(F0, WA, a2, r0, c0);
        float4 bv = *(const float4*)(c1b + c0);
#pragma unroll
        for (int i = 0; i < 2; i++)
            *(float4*)(R1 + (r0+i)*64 + c0) = make_float4(
                fmaxf(a2[i][0] + bv.x, 0.f), fmaxf(a2[i][1] + bv.y, 0.f),
                fmaxf(a2[i][2] + bv.z, 0.f), fmaxf(a2[i][3] + bv.w, 0.f));
    }
    __syncthreads();

    {
        float a2[2][4] = {};
        g24(R1, WB, a2, r0, c0);
        float4 bv = *(const float4*)(c2b + c0);
#pragma unroll
        for (int i = 0; i < 2; i++) {
            float4 f0v = *(float4*)(F0 + (r0+i)*64 + c0);
            *(float4*)(F2 + (r0+i)*64 + c0) = make_float4(
                f0v.x + a2[i][0] + bv.x, f0v.y + a2[i][1] + bv.y,
                f0v.z + a2[i][2] + bv.z, f0v.w + a2[i][3] + bv.w);
        }
    }
    __syncthreads();

#pragma unroll
    for (int half = 0; half < 2; half++) {
        for (int i = t; i < 1024; i += 256) {
            int row = i >> 4, c4 = (i & 15) * 4;
            *(float4*)(WA + row*64 + c4) = *(const float4*)(upw + row*128 + half*64 + c4);
            *(float4*)(WB + row*64 + c4) = *(const float4*)(gw  + row*128 + half*64 + c4);
        }
        __syncthreads();
        float au[2][4] = {}, ag[2][4] = {};
        g24_2B(F2, WA, WB, au, ag, r0, c0);
        float4 ub  = *(const float4*)(upb + half*64 + c0);
        float4 gb4 = *(const float4*)(gb + half*64 + c0);
#pragma unroll
        for (int i = 0; i < 2; i++) {
            float g0v = fmaxf(ag[i][0] + gb4.x, 0.f) * (au[i][0] + ub.x);
            float g1v = fmaxf(ag[i][1] + gb4.y, 0.f) * (au[i][1] + ub.y);
            float g2v = fmaxf(ag[i][2] + gb4.z, 0.f) * (au[i][2] + ub.z);
            float g3v = fmaxf(ag[i][3] + gb4.w, 0.f) * (au[i][3] + ub.w);
            *(float4*)(GU + (r0+i)*128 + half*64 + c0) = make_float4(g0v, g1v, g2v, g3v);
        }
        __syncthreads();
    }

    for (int i = t; i < 1024; i += 256) {
        *(float4*)(WA + i*4) = *(const float4*)(dw + i*4);
        *(float4*)(WB + i*4) = *(const float4*)(dw + 4096 + i*4);
    }
    __syncthreads();
    float fo[2][4];
    {
        float a2[2][4] = {};
#pragma unroll 4
        for (int k4 = 0; k4 < 128; k4 += 4) {
            const float* Bsrc = (k4 < 64) ? (WA + k4*64) : (WB + (k4-64)*64);
            float aa[2][4], bb[4][4];
#pragma unroll
            for (int i = 0; i < 2; i++)
                *(float4*)aa[i] = *(const float4*)(GU + (r0+i)*128 + k4);
#pragma unroll
            for (int kk = 0; kk < 4; kk++)
                *(float4*)bb[kk] = *(const float4*)(Bsrc + kk*64 + c0);
#pragma unroll
            for (int kk = 0; kk < 4; kk++)
#pragma unroll
                for (int i = 0; i < 2; i++)
#pragma unroll
                    for (int j = 0; j < 4; j++)
                        a2[i][j] = fmaf(aa[i][kk], bb[kk][j], a2[i][j]);
        }
        float4 bv = *(const float4*)(db + c0);
#pragma unroll
        for (int i = 0; i < 2; i++) {
            float4 f2v = *(float4*)(F2 + (r0+i)*64 + c0);
            fo[i][0] = f2v.x + fmaxf(a2[i][0] + bv.x, 0.f);
            fo[i][1] = f2v.y + fmaxf(a2[i][1] + bv.y, 0.f);
            fo[i][2] = f2v.z + fmaxf(a2[i][2] + bv.z, 0.f);
            fo[i][3] = f2v.w + fmaxf(a2[i][3] + bv.w, 0.f);
        }
    }
    __syncthreads();
#pragma unroll
    for (int i = 0; i < 2; i++)
        *(float4*)(WA + (r0+i)*64 + c0) =
            make_float4(fo[i][0], fo[i][1], fo[i][2], fo[i][3]);
    __syncthreads();

    {
        int pl_ = t >> 3;
        int q   = t & 7;
        int d0  = q * 8;
        int qg2 = qt*QT + pl_;
        if (qg2 < LL) {
            int gp = b*LL + qg2;
            int ip = pos_s[gp], in_ = neg_s[gp];
            float pl = 0.f, nl = 0.f;
#pragma unroll
            for (int d = 0; d < 8; d += 4) {
                float4 f  = *(float4*)(WA + pl_*64 + d0 + d);
                float4 ep = *(const float4*)(emb + ip*64 + d0 + d);
                float4 en = *(const float4*)(emb + in_*64 + d0 + d);
                pl += f.x*ep.x + f.y*ep.y + f.z*ep.z + f.w*ep.w;
                nl += f.x*en.x + f.y*en.y + f.z*en.z + f.w*en.w;
            }
            pl += __shfl_xor_sync(0xffffffffu, pl, 1);
            pl += __shfl_xor_sync(0xffffffffu, pl, 2);
            pl += __shfl_xor_sync(0xffffffffu, pl, 4);
            nl += __shfl_xor_sync(0xffffffffu, nl, 1);
            nl += __shfl_xor_sync(0xffffffffu, nl, 2);
            nl += __shfl_xor_sync(0xffffffffu, nl, 4);
            if (q == 0) { out[gp] = pl; out[NP + gp] = nl; }
        }
    }
}

// ============================================================
extern "C" void kernel_launch(void* const* d_in, const int* in_sizes, int n_in,
                              void* d_out, int out_size) {
    const int*   log_seqs = (const int*)  d_in[0];
    const int*   pos_seqs = (const int*)  d_in[1];
    const int*   neg_seqs = (const int*)  d_in[2];
    const float* adj      = (const float*)d_in[4];
    const float* item_emb = (const float*)d_in[5];
    const float* pos_emb  = (const float*)d_in[6];
    const float* W_item   = (const float*)d_in[7];
    const float* a_item   = (const float*)d_in[8];
    const float* W_1      = (const float*)d_in[9];
    const float* W_2      = (const float*)d_in[10];
    const float* b_attn   = (const float*)d_in[11];
    const float* co_c     = (const float*)d_in[12];
    const float* co_n     = (const float*)d_in[13];
    const float* c1w      = (const float*)d_in[14];
    const float* c1b      = (const float*)d_in[15];
    const float* c2w      = (const float*)d_in[16];
    const float* c2b      = (const float*)d_in[17];
    const float* upw      = (const float*)d_in[18];
    const float* upb      = (const float*)d_in[19];
    const float* gw       = (const float*)d_in[20];
    const float* gb       = (const float*)d_in[21];
    const float* dw       = (const float*)d_in[22];
    const float* db       = (const float*)d_in[23];
    float* out = (float*)d_out;

    static bool attr_done = false;
    if (!attr_done) {
        cudaFuncSetAttribute(k_seq2, cudaFuncAttributeMaxDynamicSharedMemorySize, 49152);
        cudaFuncSetAttribute(k_ffn3, cudaFuncAttributeMaxDynamicSharedMemorySize, 57344);
        attr_done = true;
    }

    k_h2   <<<(NI + 63) / 64, 256>>>(item_emb, W_item, a_item);
    k_adjf <<<(NI + 3) / 4, 256>>>(adj);
    k_seq2 <<<NP / 32, 256, 49152>>>(log_seqs, item_emb, pos_emb,
                                     co_c, co_n, W_1, W_2);
    dim3 sg(28, BB);
    k_score<<<sg, 256>>>(b_attn);
    dim3 fg(7, BB);
    k_ffn3 <<<fg, 256, 57344>>>(pos_seqs, neg_seqs, item_emb,
                                c1w, c1b, c2w, c2b, upw, upb,
                                gw, gb, dw, db, out);
}

// round 9
// speedup vs baseline: 1.1617x; 1.1617x over previous
#include <cuda_runtime.h>

#define NI   6001
#define DD   64
#define LL   200
#define BB   32
#define NP   (BB*LL)   // 6400 positions
#define QT   32
#define KT   32
#define CAP  192       // max nonzeros per adj row

// ---- device scratch (no allocations allowed) ----
__device__ float g_h[NI*DD];
__device__ float g_wh1[NI];
__device__ float g_wh2[NI];
__device__ float g_trans[NI*DD];
__device__ float g_gat[NI*DD];
__device__ float g_seqs[NP*DD];
__device__ float g_M1[NP*DD];
__device__ float g_M2[NP*DD];
__device__ float g_score[BB*LL*LL];

__device__ __forceinline__ float tanha(float x) {
    float t;
    asm("tanh.approx.f32 %0, %1;" : "=f"(t) : "f"(x));
    return t;
}

// ---- 4x4-tile GEMM helper (64-row blocks) ----
__device__ __forceinline__ void gemm_acc(const float* __restrict__ A,
                                         const float* __restrict__ B,
                                         float acc[4][4], int r0, int c0) {
#pragma unroll 4
    for (int k4 = 0; k4 < 64; k4 += 4) {
        float aa[4][4], bb[4][4];
#pragma unroll
        for (int i = 0; i < 4; i++)
            *(float4*)aa[i] = *(const float4*)(A + (r0+i)*64 + k4);
#pragma unroll
        for (int kk = 0; kk < 4; kk++)
            *(float4*)bb[kk] = *(const float4*)(B + (k4+kk)*64 + c0);
#pragma unroll
        for (int kk = 0; kk < 4; kk++)
#pragma unroll
            for (int i = 0; i < 4; i++)
#pragma unroll
                for (int j = 0; j < 4; j++)
                    acc[i][j] = fmaf(aa[i][kk], bb[kk][j], acc[i][j]);
    }
}

__device__ __forceinline__ void gemm_acc2B4(const float* __restrict__ A,
                                            const float* __restrict__ B1,
                                            const float* __restrict__ B2,
                                            float accP[4][4], float accQ[4][4],
                                            int r0, int c0) {
#pragma unroll 4
    for (int k4 = 0; k4 < 64; k4 += 4) {
        float aa[4][4], b1[4][4], b2[4][4];
#pragma unroll
        for (int i = 0; i < 4; i++)
            *(float4*)aa[i] = *(const float4*)(A + (r0+i)*64 + k4);
#pragma unroll
        for (int kk = 0; kk < 4; kk++) {
            *(float4*)b1[kk] = *(const float4*)(B1 + (k4+kk)*64 + c0);
            *(float4*)b2[kk] = *(const float4*)(B2 + (k4+kk)*64 + c0);
        }
#pragma unroll
        for (int kk = 0; kk < 4; kk++)
#pragma unroll
            for (int i = 0; i < 4; i++)
#pragma unroll
                for (int j = 0; j < 4; j++) {
                    accP[i][j] = fmaf(aa[i][kk], b1[kk][j], accP[i][j]);
                    accQ[i][j] = fmaf(aa[i][kk], b2[kk][j], accQ[i][j]);
                }
    }
}

// ---- 2x4-tile GEMM helpers (32-row blocks) ----
__device__ __forceinline__ void g24_2B(const float* __restrict__ A,
                                       const float* __restrict__ B1,
                                       const float* __restrict__ B2,
                                       float accP[2][4], float accQ[2][4],
                                       int r0, int c0) {
#pragma unroll 4
    for (int k4 = 0; k4 < 64; k4 += 4) {
        float aa[2][4], b1[4][4], b2[4][4];
#pragma unroll
        for (int i = 0; i < 2; i++)
            *(float4*)aa[i] = *(const float4*)(A + (r0+i)*64 + k4);
#pragma unroll
        for (int kk = 0; kk < 4; kk++) {
            *(float4*)b1[kk] = *(const float4*)(B1 + (k4+kk)*64 + c0);
            *(float4*)b2[kk] = *(const float4*)(B2 + (k4+kk)*64 + c0);
        }
#pragma unroll
        for (int kk = 0; kk < 4; kk++)
#pragma unroll
            for (int i = 0; i < 2; i++)
#pragma unroll
                for (int j = 0; j < 4; j++) {
                    accP[i][j] = fmaf(aa[i][kk], b1[kk][j], accP[i][j]);
                    accQ[i][j] = fmaf(aa[i][kk], b2[kk][j], accQ[i][j]);
                }
    }
}

__device__ __forceinline__ void g24_2A(const float* __restrict__ A1,
                                       const float* __restrict__ A2,
                                       const float* __restrict__ B1,
                                       const float* __restrict__ B2,
                                       float acc[2][4], int r0, int c0) {
#pragma unroll 4
    for (int k4 = 0; k4 < 64; k4 += 4) {
        float a1[2][4], a2[2][4], b1[4][4], b2[4][4];
#pragma unroll
        for (int i = 0; i < 2; i++) {
            *(float4*)a1[i] = *(const float4*)(A1 + (r0+i)*64 + k4);
            *(float4*)a2[i] = *(const float4*)(A2 + (r0+i)*64 + k4);
        }
#pragma unroll
        for (int kk = 0; kk < 4; kk++) {
            *(float4*)b1[kk] = *(const float4*)(B1 + (k4+kk)*64 + c0);
            *(float4*)b2[kk] = *(const float4*)(B2 + (k4+kk)*64 + c0);
        }
#pragma unroll
        for (int kk = 0; kk < 4; kk++)
#pragma unroll
            for (int i = 0; i < 2; i++)
#pragma unroll
                for (int j = 0; j < 4; j++) {
                    acc[i][j] = fmaf(a1[i][kk], b1[kk][j], acc[i][j]);
                    acc[i][j] = fmaf(a2[i][kk], b2[kk][j], acc[i][j]);
                }
    }
}

// ============================================================
// K1: tiled  h = emb@W ; wh1/wh2 fused.  grid ceil(NI/64)
// ============================================================
__global__ __launch_bounds__(256) void k_h2(const float* __restrict__ emb,
                                            const float* __restrict__ W,
                                            const float* __restrict__ a) {
    __shared__ float Xs[64*64];
    __shared__ float Ws[64*64];
    int t = threadIdx.x;
    int base = blockIdx.x * 64;
    for (int i = t; i < 1024; i += 256) {
        int row = i >> 4, c4 = (i & 15) * 4;
        float4 v = make_float4(0.f,0.f,0.f,0.f);
        if (base + row < NI) v = *(const float4*)(emb + (base+row)*64 + c4);
        *(float4*)(Xs + row*64 + c4) = v;
        *(float4*)(Ws + i*4) = *(const float4*)(W + i*4);
    }
    __syncthreads();
    int tx = t & 15, ty = t >> 4;
    int r0 = ty*4, c0 = tx*4;
    float acc[4][4] = {};
    gemm_acc(Xs, Ws, acc, r0, c0);

    float4 a1v = *(const float4*)(a + c0);
    float4 a2v = *(const float4*)(a + 64 + c0);
#pragma unroll
    for (int i = 0; i < 4; i++) {
        int gr = base + r0 + i;
        if (gr < NI)
            *(float4*)(g_h + gr*64 + c0) =
                make_float4(acc[i][0], acc[i][1], acc[i][2], acc[i][3]);
        float p1 = acc[i][0]*a1v.x + acc[i][1]*a1v.y + acc[i][2]*a1v.z + acc[i][3]*a1v.w;
        float p2 = acc[i][0]*a2v.x + acc[i][1]*a2v.y + acc[i][2]*a2v.z + acc[i][3]*a2v.w;
#pragma unroll
        for (int o = 8; o > 0; o >>= 1) {
            p1 += __shfl_xor_sync(0xffffffffu, p1, o);
            p2 += __shfl_xor_sync(0xffffffffu, p2, o);
        }
        if (tx == 0 && gr < NI) { g_wh1[gr] = p1; g_wh2[gr] = p2; }
    }
}

// ============================================================
// K2 (fused, R7 version): stream+compact adj row to SMEM, gather+apply.
// Warp per row; grid ceil(NI/8) x 256.
// ============================================================
__device__ __forceinline__ int emit4(float4 v, int colbase, int cnt,
                                     int* cols, float* vals,
                                     int lane, unsigned lt) {
    unsigned mx = __ballot_sync(0xffffffffu, v.x != 0.f);
    unsigned my = __ballot_sync(0xffffffffu, v.y != 0.f);
    unsigned mz = __ballot_sync(0xffffffffu, v.z != 0.f);
    unsigned mw = __ballot_sync(0xffffffffu, v.w != 0.f);
    if ((mx | my | mz | mw) == 0u) return cnt;
    int cx = __popc(mx), cy = __popc(my), cz = __popc(mz), cw = __popc(mw);
    int col = colbase + lane*4;
    if (v.x != 0.f) {
        int w = cnt + __popc(mx & lt);
        if (w < CAP) { cols[w] = col;     vals[w] = v.x; }
    }
    if (v.y != 0.f) {
        int w = cnt + cx + __popc(my & lt);
        if (w < CAP) { cols[w] = col + 1; vals[w] = v.y; }
    }
    if (v.z != 0.f) {
        int w = cnt + cx + cy + __popc(mz & lt);
        if (w < CAP) { cols[w] = col + 2; vals[w] = v.z; }
    }
    if (v.w != 0.f) {
        int w = cnt + cx + cy + cz + __popc(mw & lt);
        if (w < CAP) { cols[w] = col + 3; vals[w] = v.w; }
    }
    return cnt + cx + cy + cz + cw;
}

__device__ __forceinline__ void apply_one(int j, float av, int lane, float w1,
                                          float& t0, float& t1,
                                          float& g0, float& g1, float& den) {
    float hj0 = g_h[j*DD + lane];
    float hj1 = g_h[j*DD + 32 + lane];
    float e = w1 + g_wh2[j];
    e = (e > 0.f) ? e : 0.01f * e;
    float w = __expf(e);
    t0 = fmaf(av, hj0, t0);
    t1 = fmaf(av, hj1, t1);
    g0 = fmaf(w, hj0, g0);
    g1 = fmaf(w, hj1, g1);
    den += w;
}

__global__ __launch_bounds__(256) void k_adjf(const float* __restrict__ adj) {
    __shared__ int   scols[8*CAP];
    __shared__ float svals[8*CAP];
    int warp = threadIdx.x >> 5;
    int lane = threadIdx.x & 31;
    int row  = blockIdx.x * 8 + warp;
    if (row >= NI) return;

    unsigned lt = (1u << lane) - 1u;
    int*   cols = scols + warp*CAP;
    float* vals = svals + warp*CAP;
    const float* arow = adj + (long long)row * NI;
    int cnt = 0;

    int p0 = (4 - (row & 3)) & 3;
    {
        float a = (lane < p0) ? arow[lane] : 0.f;
        unsigned m = __ballot_sync(0xffffffffu, a != 0.f);
        if (a != 0.f) {
            int off = __popc(m & lt);
            if (cnt + off < CAP) { cols[cnt+off] = lane; vals[cnt+off] = a; }
        }
        cnt += __popc(m);
    }
    const float4* a4 = (const float4*)(arow + p0);
    int n4 = (NI - p0) >> 2;
    int i = 0;
    for (; i + 128 <= n4; i += 128) {
        float4 v0 = __ldcs(&a4[i       + lane]);
        float4 v1 = __ldcs(&a4[i +  32 + lane]);
        float4 v2 = __ldcs(&a4[i +  64 + lane]);
        float4 v3 = __ldcs(&a4[i +  96 + lane]);
        cnt = emit4(v0, p0 + (i      )*4, cnt, cols, vals, lane, lt);
        cnt = emit4(v1, p0 + (i +  32)*4, cnt, cols, vals, lane, lt);
        cnt = emit4(v2, p0 + (i +  64)*4, cnt, cols, vals, lane, lt);
        cnt = emit4(v3, p0 + (i +  96)*4, cnt, cols, vals, lane, lt);
    }
    for (; i < n4; i += 32) {
        float4 v = (i + lane < n4) ? __ldcs(&a4[i + lane])
                                   : make_float4(0.f,0.f,0.f,0.f);
        cnt = emit4(v, p0 + i*4, cnt, cols, vals, lane, lt);
    }
    int st = p0 + n4*4;
    {
        int j = st + lane;
        float a = (j < NI) ? arow[j] : 0.f;
        unsigned m = __ballot_sync(0xffffffffu, a != 0.f);
        if (a != 0.f) {
            int off = __popc(m & lt);
            if (cnt + off < CAP) { cols[cnt+off] = j; vals[cnt+off] = a; }
        }
        cnt += __popc(m);
    }
    int n = (cnt < CAP) ? cnt : CAP;

    float w1 = g_wh1[row];
    float t0 = 0.f, t1 = 0.f, g0 = 0.f, g1 = 0.f, den = 0.f;
    int k = 0;
    for (; k + 8 <= n; k += 8) {
        int   j0 = cols[k],   j1 = cols[k+1], j2 = cols[k+2], j3 = cols[k+3];
        int   j4 = cols[k+4], j5 = cols[k+5], j6 = cols[k+6], j7 = cols[k+7];
        float a0 = vals[k],   a1 = vals[k+1], a2 = vals[k+2], a3 = vals[k+3];
        float a4v = vals[k+4], a5 = vals[k+5], a6 = vals[k+6], a7 = vals[k+7];
        apply_one(j0, a0, lane, w1, t0, t1, g0, g1, den);
        apply_one(j1, a1, lane, w1, t0, t1, g0, g1, den);
        apply_one(j2, a2, lane, w1, t0, t1, g0, g1, den);
        apply_one(j3, a3, lane, w1, t0, t1, g0, g1, den);
        apply_one(j4, a4v, lane, w1, t0, t1, g0, g1, den);
        apply_one(j5, a5, lane, w1, t0, t1, g0, g1, den);
        apply_one(j6, a6, lane, w1, t0, t1, g0, g1, den);
        apply_one(j7, a7, lane, w1, t0, t1, g0, g1, den);
    }
    for (; k < n; k++) apply_one(cols[k], vals[k], lane, w1, t0, t1, g0, g1, den);

    float inv = 1.f / den;
    g_trans[row*DD + lane]      = t0;
    g_trans[row*DD + 32 + lane] = t1;
    g_gat[row*DD + lane]        = g0 * inv;
    g_gat[row*DD + 32 + lane]   = g1 * inv;
}

// ============================================================
// K3: tiled seq — 32 positions/block, 48KB dyn smem, grid 200.
// ============================================================
__global__ __launch_bounds__(256) void k_seq2(const int* __restrict__ logs,
                                              const float* __restrict__ emb,
                                              const float* __restrict__ posT,
                                              const float* __restrict__ cc,
                                              const float* __restrict__ cn,
                                              const float* __restrict__ W1,
                                              const float* __restrict__ W2) {
    extern __shared__ float sm[];
    float* GR = sm;
    float* TR = sm + 2048;
    float* WA = sm + 4096;
    float* WB = sm + 8192;
    __shared__ int ids[32];

    int t = threadIdx.x;
    int p0 = blockIdx.x * 32;
    if (t < 32) ids[t] = logs[p0 + t];
    for (int i = t; i < 1024; i += 256) {
        *(float4*)(WA + i*4) = *(const float4*)(cc + i*4);
        *(float4*)(WB + i*4) = *(const float4*)(cn + i*4);
    }
    __syncthreads();
    for (int i = t; i < 512; i += 256) {
        int row = i >> 4, c4 = (i & 15) * 4;
        int id = ids[row];
        *(float4*)(GR + row*64 + c4) = *(const float4*)(g_gat + id*64 + c4);
        *(float4*)(TR + row*64 + c4) = *(const float4*)(g_trans + id*64 + c4);
    }
    __syncthreads();

    int tx = t & 15, ty = t >> 4;
    int r0 = ty*2, c0 = tx*4;
    float acc[2][4] = {};
    g24_2A(GR, TR, WA, WB, acc, r0, c0);
    __syncthreads();

    for (int i = t; i < 1024; i += 256) {
        *(float4*)(WA + i*4) = *(const float4*)(W1 + i*4);
        *(float4*)(WB + i*4) = *(const float4*)(W2 + i*4);
    }
#pragma unroll
    for (int i = 0; i < 2; i++) {
        int r = r0 + i;
        int id = ids[r];
        int p  = p0 + r;
        int l  = p % LL;
        float4 gv = *(float4*)(GR + r*64 + c0);
        float4 tv = *(float4*)(TR + r*64 + c0);
        float4 ev = *(const float4*)(emb + id*64 + c0);
        float4 pv = make_float4(0.f,0.f,0.f,0.f);
        if (id != 0) pv = *(const float4*)(posT + l*64 + c0);
        float s0 = tv.x + ev.x, s1 = tv.y + ev.y, s2 = tv.z + ev.z, s3 = tv.w + ev.w;
        float c0f = __fdividef(1.f, 1.f + __expf(-acc[i][0]));
        float c1f = __fdividef(1.f, 1.f + __expf(-acc[i][1]));
        float c2f = __fdividef(1.f, 1.f + __expf(-acc[i][2]));
        float c3f = __fdividef(1.f, 1.f + __expf(-acc[i][3]));
        s0 = fmaf(c0f, gv.x - tv.x, s0);
        s1 = fmaf(c1f, gv.y - tv.y, s1);
        s2 = fmaf(c2f, gv.z - tv.z, s2);
        s3 = fmaf(c3f, gv.w - tv.w, s3);
        *(float4*)(g_seqs + p*64 + c0) = make_float4(s0, s1, s2, s3);
        *(float4*)(GR + r*64 + c0) =
            make_float4(s0 + pv.x, s1 + pv.y, s2 + pv.z, s3 + pv.w);
    }
    __syncthreads();

    float m1[2][4] = {}, m2[2][4] = {};
    g24_2B(GR, WA, WB, m1, m2, r0, c0);
#pragma unroll
    for (int i = 0; i < 2; i++) {
        int p = p0 + r0 + i;
        *(float4*)(g_M1 + p*64 + c0) =
            make_float4(0.5f*m1[i][0], 0.5f*m1[i][1], 0.5f*m1[i][2], 0.5f*m1[i][3]);
        *(float4*)(g_M2 + p*64 + c0) =
            make_float4(0.5f*m2[i][0], 0.5f*m2[i][1], 0.5f*m2[i][2], 0.5f*m2[i][3]);
    }
}

// ============================================================
// K4a: score tiles — one block per causal 32x32 tile.
// ============================================================
__global__ __launch_bounds__(256) void k_score(const float* __restrict__ battn) {
    int b   = blockIdx.y;
    int tid = blockIdx.x;
    int qt = 0, base = 0;
    while (base + qt + 1 <= tid) { base += qt + 1; qt++; }
    int kt = tid - base;
    int t = threadIdx.x;

    __shared__ float m1s[32*68];
    __shared__ float m2s[32*64];
    __shared__ float bs2[64];

    for (int i = t; i < 512; i += 256) {
        int row = i >> 4, c4 = (i & 15)*4;
        int qg = qt*QT + row;
        float4 v = (qg < LL) ? *(const float4*)(g_M1 + (b*LL+qg)*64 + c4)
                             : make_float4(0.f,0.f,0.f,0.f);
        *(float4*)(m1s + row*68 + c4) = v;
        int kg = kt*KT + row;
        float4 w = (kg < LL) ? *(const float4*)(g_M2 + (b*LL+kg)*64 + c4)
                             : make_float4(0.f,0.f,0.f,0.f);
        *(float4*)(m2s + row*64 + c4) = w;
    }
    if (t < 64) bs2[t] = 0.5f * battn[t];
    __syncthreads();

    int ql = t & 31;
    int kb = (t >> 5) << 2;
    int qg = qt*QT + ql;

    float hs = 0.f;
#pragma unroll
    for (int d = 0; d < 64; d += 4) {
        float4 bv = *(float4*)(bs2 + d);
        hs += bv.x + bv.y + bv.z + bv.w;
    }

    float s0 = 0.f, s1 = 0.f, s2 = 0.f, s3 = 0.f;
#pragma unroll 4
    for (int d4 = 0; d4 < 64; d4 += 4) {
        float4 m1v = *(float4*)(m1s + ql*68 + d4);
        float4 b2  = *(float4*)(bs2 + d4);
        float4 k0  = *(float4*)(m2s + (kb+0)*64 + d4);
        float4 k1  = *(float4*)(m2s + (kb+1)*64 + d4);
        float4 k2  = *(float4*)(m2s + (kb+2)*64 + d4);
        float4 k3  = *(float4*)(m2s + (kb+3)*64 + d4);
        s0 = fmaf(b2.x, tanha(m1v.x + k0.x), s0);
        s1 = fmaf(b2.x, tanha(m1v.x + k1.x), s1);
        s2 = fmaf(b2.x, tanha(m1v.x + k2.x), s2);
        s3 = fmaf(b2.x, tanha(m1v.x + k3.x), s3);
        s0 = fmaf(b2.y, tanha(m1v.y + k0.y), s0);
        s1 = fmaf(b2.y, tanha(m1v.y + k1.y), s1);
        s2 = fmaf(b2.y, tanha(m1v.y + k2.y), s2);
        s3 = fmaf(b2.y, tanha(m1v.y + k3.y), s3);
        s0 = fmaf(b2.z, tanha(m1v.z + k0.z), s0);
        s1 = fmaf(b2.z, tanha(m1v.z + k1.z), s1);
        s2 = fmaf(b2.z, tanha(m1v.z + k2.z), s2);
        s3 = fmaf(b2.z, tanha(m1v.z + k3.z), s3);
        s0 = fmaf(b2.w, tanha(m1v.w + k0.w), s0);
        s1 = fmaf(b2.w, tanha(m1v.w + k1.w), s1);
        s2 = fmaf(b2.w, tanha(m1v.w + k2.w), s2);
        s3 = fmaf(b2.w, tanha(m1v.w + k3.w), s3);
    }
    if (qg < LL) {
        int kg0 = kt*KT + kb;
        float* srow = &g_score[((long long)b*LL + qg)*LL];
        if (kg0+0 < LL) srow[kg0+0] = (kg0+0 <= qg) ? s0 + hs : 0.f;
        if (kg0+1 < LL) srow[kg0+1] = (kg0+1 <= qg) ? s1 + hs : 0.f;
        if (kg0+2 < LL) srow[kg0+2] = (kg0+2 <= qg) ? s2 + hs : 0.f;
        if (kg0+3 < LL) srow[kg0+3] = (kg0+3 <= qg) ? s3 + hs : 0.f;
    }
}

// ============================================================
// K5 (balanced fused): block = (pair of q-tiles {6-2p, 5-2p}, b).
// grid (4, BB), 256 threads, 80KB dyn smem, 64 rows per block.
// Phase A stages each k-tile ONCE for both q-tiles (scores are
// causally zero-masked, so tile B's extra k-tiles contribute 0).
// ============================================================
__global__ __launch_bounds__(256) void k_ffn4(const int* __restrict__ pos_s,
                                              const int* __restrict__ neg_s,
                                              const float* __restrict__ emb,
                                              const float* __restrict__ c1w,
                                              const float* __restrict__ c1b,
                                              const float* __restrict__ c2w,
                                              const float* __restrict__ c2b,
                                              const float* __restrict__ upw,
                                              const float* __restrict__ upb,
                                              const float* __restrict__ gw,
                                              const float* __restrict__ gb,
                                              const float* __restrict__ dw,
                                              const float* __restrict__ db,
                                              float* __restrict__ out) {
    extern __shared__ float sm[];
    float* F0 = sm;            // [64][64] (GU aliases F0+R1)
    float* R1 = sm + 4096;
    float* F2 = sm + 8192;
    float* WA = sm + 12288;    // 4096
    float* WB = sm + 16384;    // 4096
    float* GU = sm;            // [64][128]
    float* seqss = WA;         // phase A [32][64]
    float* scsA  = WB;         // phase A [32][36]
    float* scsB  = WB + 1152;  // phase A [32][36]

    int t = threadIdx.x;
    int b = blockIdx.y;
    int p = blockIdx.x;            // 0..3
    int qtA = 6 - 2*p;             // 6,4,2,0
    int qtB = qtA - 1;             // 5,3,1,-1

    // ---- phase A: F0[0:32] = tileA, F0[32:64] = tileB ----
    int qrow  = t >> 3;            // 0..31
    int dbase = (t & 7) << 3;
    float accA[8], accB[8];
#pragma unroll
    for (int i = 0; i < 8; i++) { accA[i] = 0.f; accB[i] = 0.f; }

    for (int kt = 0; kt <= qtA; kt++) {
        __syncthreads();
        for (int i = t; i < 512; i += 256) {
            int kl = i >> 4, c4 = (i & 15) * 4;
            int kg = kt*KT + kl;
            float4 v = (kg < LL) ? *(const float4*)(g_seqs + (b*LL+kg)*64 + c4)
                                 : make_float4(0.f,0.f,0.f,0.f);
            *(float4*)(seqss + kl*64 + c4) = v;
        }
        {
            int ql = t >> 3, c4 = (t & 7) * 4;
            int kg = kt*KT + c4;
            int qgA = qtA*QT + ql;
            float4 v = (qgA < LL && kg < LL)
                     ? *(const float4*)(g_score + ((long long)b*LL + qgA)*LL + kg)
                     : make_float4(0.f,0.f,0.f,0.f);
            *(float4*)(scsA + ql*36 + c4) = v;
            float4 w = make_float4(0.f,0.f,0.f,0.f);
            if (qtB >= 0 && kg < LL) {
                int qgB = qtB*QT + ql;
                w = *(const float4*)(g_score + ((long long)b*LL + qgB)*LL + kg);
            }
            *(float4*)(scsB + ql*36 + c4) = w;
        }
        __syncthreads();
#pragma unroll 4
        for (int k = 0; k < KT; k++) {
            float svA = scsA[qrow*36 + k];
            float svB = scsB[qrow*36 + k];
            float4 v0 = *(float4*)(seqss + k*64 + dbase);
            float4 v1 = *(float4*)(seqss + k*64 + dbase + 4);
            accA[0] = fmaf(svA, v0.x, accA[0]);
            accA[1] = fmaf(svA, v0.y, accA[1]);
            accA[2] = fmaf(svA, v0.z, accA[2]);
            accA[3] = fmaf(svA, v0.w, accA[3]);
            accA[4] = fmaf(svA, v1.x, accA[4]);
            accA[5] = fmaf(svA, v1.y, accA[5]);
            accA[6] = fmaf(svA, v1.z, accA[6]);
            accA[7] = fmaf(svA, v1.w, accA[7]);
            accB[0] = fmaf(svB, v0.x, accB[0]);
            accB[1] = fmaf(svB, v0.y, accB[1]);
            accB[2] = fmaf(svB, v0.z, accB[2]);
            accB[3] = fmaf(svB, v0.w, accB[3]);
            accB[4] = fmaf(svB, v1.x, accB[4]);
            accB[5] = fmaf(svB, v1.y, accB[5]);
            accB[6] = fmaf(svB, v1.z, accB[6]);
            accB[7] = fmaf(svB, v1.w, accB[7]);
        }
    }
    __syncthreads();
    *(float4*)(F0 + qrow*64 + dbase)          = make_float4(accA[0], accA[1], accA[2], accA[3]);
    *(float4*)(F0 + qrow*64 + dbase + 4)      = make_float4(accA[4], accA[5], accA[6], accA[7]);
    *(float4*)(F0 + (32+qrow)*64 + dbase)     = make_float4(accB[0], accB[1], accB[2], accB[3]);
    *(float4*)(F0 + (32+qrow)*64 + dbase + 4) = make_float4(accB[4], accB[5], accB[6], accB[7]);
    __syncthreads();

    // ---- FFN path (64 rows, 4x4 tiles) ----
    int tx = t & 15, ty = t >> 4;
    int r0 = ty*4, c0 = tx*4;

    for (int i = t; i < 1024; i += 256) {
        *(float4*)(WA + i*4) = *(const float4*)(c1w + i*4);
        *(float4*)(WB + i*4) = *(const float4*)(c2w + i*4);
    }
    __syncthreads();

    // GEMM1: R1 = relu(F0@c1w + c1b)
    {
        float a2[4][4] = {};
        gemm_acc(F0, WA, a2, r0, c0);
        float4 bv = *(const float4*)(c1b + c0);
#pragma unroll
        for (int i = 0; i < 4; i++)
            *(float4*)(R1 + (r0+i)*64 + c0) = make_float4(
                fmaxf(a2[i][0] + bv.x, 0.f), fmaxf(a2[i][1] + bv.y, 0.f),
                fmaxf(a2[i][2] + bv.z, 0.f), fmaxf(a2[i][3] + bv.w, 0.f));
    }
    __syncthreads();

    // GEMM2: F2 = F0 + R1@c2w + c2b
    {
        float a2[4][4] = {};
        gemm_acc(R1, WB, a2, r0, c0);
        float4 bv = *(const float4*)(c2b + c0);
#pragma unroll
        for (int i = 0; i < 4; i++) {
            float4 f0v = *(float4*)(F0 + (r0+i)*64 + c0);
            *(float4*)(F2 + (r0+i)*64 + c0) = make_float4(
                f0v.x + a2[i][0] + bv.x, f0v.y + a2[i][1] + bv.y,
                f0v.z + a2[i][2] + bv.z, f0v.w + a2[i][3] + bv.w);
        }
    }
    __syncthreads();

    // GEMM3 (two halves): GU = relu(F2@gw + gb) * (F2@upw + upb)
#pragma unroll
    for (int half = 0; half < 2; half++) {
        for (int i = t; i < 1024; i += 256) {
            int row = i >> 4, c4 = (i & 15) * 4;
            *(float4*)(WA + row*64 + c4) = *(const float4*)(upw + row*128 + half*64 + c4);
            *(float4*)(WB + row*64 + c4) = *(const float4*)(gw  + row*128 + half*64 + c4);
        }
        __syncthreads();
        float au[4][4] = {}, ag[4][4] = {};
        gemm_acc2B4(F2, WA, WB, au, ag, r0, c0);
        float4 ub  = *(const float4*)(upb + half*64 + c0);
        float4 gb4 = *(const float4*)(gb + half*64 + c0);
#pragma unroll
        for (int i = 0; i < 4; i++) {
            float g0v = fmaxf(ag[i][0] + gb4.x, 0.f) * (au[i][0] + ub.x);
            float g1v = fmaxf(ag[i][1] + gb4.y, 0.f) * (au[i][1] + ub.y);
            float g2v = fmaxf(ag[i][2] + gb4.z, 0.f) * (au[i][2] + ub.z);
            float g3v = fmaxf(ag[i][3] + gb4.w, 0.f) * (au[i][3] + ub.w);
            *(float4*)(GU + (r0+i)*128 + half*64 + c0) = make_float4(g0v, g1v, g2v, g3v);
        }
        __syncthreads();
    }

    // GEMM4: dn = GU@dw (K=128), fo = F2 + relu(dn + db)
    for (int i = t; i < 1024; i += 256) {
        *(float4*)(WA + i*4) = *(const float4*)(dw + i*4);
        *(float4*)(WB + i*4) = *(const float4*)(dw + 4096 + i*4);
    }
    __syncthreads();
    float fo[4][4];
    {
        float a2[4][4] = {};
#pragma unroll 4
        for (int k4 = 0; k4 < 128; k4 += 4) {
            const float* Bsrc = (k4 < 64) ? (WA + k4*64) : (WB + (k4-64)*64);
            float aa[4][4], bb[4][4];
#pragma unroll
            for (int i = 0; i < 4; i++)
                *(float4*)aa[i] = *(const float4*)(GU + (r0+i)*128 + k4);
#pragma unroll
            for (int kk = 0; kk < 4; kk++)
                *(float4*)bb[kk] = *(const float4*)(Bsrc + kk*64 + c0);
#pragma unroll
            for (int kk = 0; kk < 4; kk++)
#pragma unroll
                for (int i = 0; i < 4; i++)
#pragma unroll
                    for (int j = 0; j < 4; j++)
                        a2[i][j] = fmaf(aa[i][kk], bb[kk][j], a2[i][j]);
        }
        float4 bv = *(const float4*)(db + c0);
#pragma unroll
        for (int i = 0; i < 4; i++) {
            float4 f2v = *(float4*)(F2 + (r0+i)*64 + c0);
            fo[i][0] = f2v.x + fmaxf(a2[i][0] + bv.x, 0.f);
            fo[i][1] = f2v.y + fmaxf(a2[i][1] + bv.y, 0.f);
            fo[i][2] = f2v.z + fmaxf(a2[i][2] + bv.z, 0.f);
            fo[i][3] = f2v.w + fmaxf(a2[i][3] + bv.w, 0.f);
        }
    }
    __syncthreads();     // all GEMM4 reads done; reuse WA for fo
#pragma unroll
    for (int i = 0; i < 4; i++)
        *(float4*)(WA + (r0+i)*64 + c0) =
            make_float4(fo[i][0], fo[i][1], fo[i][2], fo[i][3]);
    __syncthreads();

    // logits: 4 threads per row (64 rows)
    {
        int r  = t >> 2;
        int q  = t & 3;
        int d0 = q * 16;
        int qg = (r < 32) ? (qtA*QT + r)
                          : ((qtB >= 0) ? (qtB*QT + r - 32) : LL);
        if (qg < LL) {
            int gp = b*LL + qg;
            int ip = pos_s[gp], in_ = neg_s[gp];
            float pl = 0.f, nl = 0.f;
#pragma unroll
            for (int d = 0; d < 16; d += 4) {
                float4 f  = *(float4*)(WA + r*64 + d0 + d);
                float4 ep = *(const float4*)(emb + ip*64 + d0 + d);
                float4 en = *(const float4*)(emb + in_*64 + d0 + d);
                pl += f.x*ep.x + f.y*ep.y + f.z*ep.z + f.w*ep.w;
                nl += f.x*en.x + f.y*en.y + f.z*en.z + f.w*en.w;
            }
            pl += __shfl_xor_sync(0xffffffffu, pl, 1);
            pl += __shfl_xor_sync(0xffffffffu, pl, 2);
            nl += __shfl_xor_sync(0xffffffffu, nl, 1);
            nl += __shfl_xor_sync(0xffffffffu, nl, 2);
            if (q == 0) { out[gp] = pl; out[NP + gp] = nl; }
        }
    }
}

// ============================================================
extern "C" void kernel_launch(void* const* d_in, const int* in_sizes, int n_in,
                              void* d_out, int out_size) {
    const int*   log_seqs = (const int*)  d_in[0];
    const int*   pos_seqs = (const int*)  d_in[1];
    const int*   neg_seqs = (const int*)  d_in[2];
    const float* adj      = (const float*)d_in[4];
    const float* item_emb = (const float*)d_in[5];
    const float* pos_emb  = (const float*)d_in[6];
    const float* W_item   = (const float*)d_in[7];
    const float* a_item   = (const float*)d_in[8];
    const float* W_1      = (const float*)d_in[9];
    const float* W_2      = (const float*)d_in[10];
    const float* b_attn   = (const float*)d_in[11];
    const float* co_c     = (const float*)d_in[12];
    const float* co_n     = (const float*)d_in[13];
    const float* c1w      = (const float*)d_in[14];
    const float* c1b      = (const float*)d_in[15];
    const float* c2w      = (const float*)d_in[16];
    const float* c2b      = (const float*)d_in[17];
    const float* upw      = (const float*)d_in[18];
    const float* upb      = (const float*)d_in[19];
    const float* gw       = (const float*)d_in[20];
    const float* gb       = (const float*)d_in[21];
    const float* dw       = (const float*)d_in[22];
    const float* db       = (const float*)d_in[23];
    float* out = (float*)d_out;

    static bool attr_done = false;
    if (!attr_done) {
        cudaFuncSetAttribute(k_seq2, cudaFuncAttributeMaxDynamicSharedMemorySize, 49152);
        cudaFuncSetAttribute(k_ffn4, cudaFuncAttributeMaxDynamicSharedMemorySize, 81920);
        attr_done = true;
    }

    k_h2   <<<(NI + 63) / 64, 256>>>(item_emb, W_item, a_item);
    k_adjf <<<(NI + 7) / 8, 256>>>(adj);
    k_seq2 <<<NP / 32, 256, 49152>>>(log_seqs, item_emb, pos_emb,
                                     co_c, co_n, W_1, W_2);
    dim3 sg(28, BB);
    k_score<<<sg, 256>>>(b_attn);
    dim3 fg(4, BB);
    k_ffn4 <<<fg, 256, 81920>>>(pos_seqs, neg_seqs, item_emb,
                                c1w, c1b, c2w, c2b, upw, upb,
                                gw, gb, dw, db, out);
}

// round 10
// speedup vs baseline: 1.2032x; 1.0358x over previous
#include <cuda_runtime.h>

#define NI   6001
#define DD   64
#define LL   200
#define BB   32
#define NP   (BB*LL)   // 6400 positions
#define QT   32
#define KT   32
#define CAP  192       // max nonzeros per adj row

// ---- device scratch (no allocations allowed) ----
__device__ float g_h[NI*DD];
__device__ float g_wh1[NI];
__device__ float g_wh2[NI];
__device__ float g_trans[NI*DD];
__device__ float g_gat[NI*DD];
__device__ float g_seqs[NP*DD];
__device__ float g_M1[NP*DD];
__device__ float g_M2[NP*DD];
__device__ float g_score[BB*LL*LL];
__device__ int   g_used[NI];

__device__ __forceinline__ float tanha(float x) {
    float t;
    asm("tanh.approx.f32 %0, %1;" : "=f"(t) : "f"(x));
    return t;
}

// ---- 4x4-tile GEMM helper (64-row blocks) ----
__device__ __forceinline__ void gemm_acc(const float* __restrict__ A,
                                         const float* __restrict__ B,
                                         float acc[4][4], int r0, int c0) {
#pragma unroll 4
    for (int k4 = 0; k4 < 64; k4 += 4) {
        float aa[4][4], bb[4][4];
#pragma unroll
        for (int i = 0; i < 4; i++)
            *(float4*)aa[i] = *(const float4*)(A + (r0+i)*64 + k4);
#pragma unroll
        for (int kk = 0; kk < 4; kk++)
            *(float4*)bb[kk] = *(const float4*)(B + (k4+kk)*64 + c0);
#pragma unroll
        for (int kk = 0; kk < 4; kk++)
#pragma unroll
            for (int i = 0; i < 4; i++)
#pragma unroll
                for (int j = 0; j < 4; j++)
                    acc[i][j] = fmaf(aa[i][kk], bb[kk][j], acc[i][j]);
    }
}

__device__ __forceinline__ void gemm_acc2B4(const float* __restrict__ A,
                                            const float* __restrict__ B1,
                                            const float* __restrict__ B2,
                                            float accP[4][4], float accQ[4][4],
                                            int r0, int c0) {
#pragma unroll 4
    for (int k4 = 0; k4 < 64; k4 += 4) {
        float aa[4][4], b1[4][4], b2[4][4];
#pragma unroll
        for (int i = 0; i < 4; i++)
            *(float4*)aa[i] = *(const float4*)(A + (r0+i)*64 + k4);
#pragma unroll
        for (int kk = 0; kk < 4; kk++) {
            *(float4*)b1[kk] = *(const float4*)(B1 + (k4+kk)*64 + c0);
            *(float4*)b2[kk] = *(const float4*)(B2 + (k4+kk)*64 + c0);
        }
#pragma unroll
        for (int kk = 0; kk < 4; kk++)
#pragma unroll
            for (int i = 0; i < 4; i++)
#pragma unroll
                for (int j = 0; j < 4; j++) {
                    accP[i][j] = fmaf(aa[i][kk], b1[kk][j], accP[i][j]);
                    accQ[i][j] = fmaf(aa[i][kk], b2[kk][j], accQ[i][j]);
                }
    }
}

// ---- 2x4-tile GEMM helpers (32-row blocks) ----
__device__ __forceinline__ void g24_2B(const float* __restrict__ A,
                                       const float* __restrict__ B1,
                                       const float* __restrict__ B2,
                                       float accP[2][4], float accQ[2][4],
                                       int r0, int c0) {
#pragma unroll 4
    for (int k4 = 0; k4 < 64; k4 += 4) {
        float aa[2][4], b1[4][4], b2[4][4];
#pragma unroll
        for (int i = 0; i < 2; i++)
            *(float4*)aa[i] = *(const float4*)(A + (r0+i)*64 + k4);
#pragma unroll
        for (int kk = 0; kk < 4; kk++) {
            *(float4*)b1[kk] = *(const float4*)(B1 + (k4+kk)*64 + c0);
            *(float4*)b2[kk] = *(const float4*)(B2 + (k4+kk)*64 + c0);
        }
#pragma unroll
        for (int kk = 0; kk < 4; kk++)
#pragma unroll
            for (int i = 0; i < 2; i++)
#pragma unroll
                for (int j = 0; j < 4; j++) {
                    accP[i][j] = fmaf(aa[i][kk], b1[kk][j], accP[i][j]);
                    accQ[i][j] = fmaf(aa[i][kk], b2[kk][j], accQ[i][j]);
                }
    }
}

__device__ __forceinline__ void g24_2A(const float* __restrict__ A1,
                                       const float* __restrict__ A2,
                                       const float* __restrict__ B1,
                                       const float* __restrict__ B2,
                                       float acc[2][4], int r0, int c0) {
#pragma unroll 4
    for (int k4 = 0; k4 < 64; k4 += 4) {
        float a1[2][4], a2[2][4], b1[4][4], b2[4][4];
#pragma unroll
        for (int i = 0; i < 2; i++) {
            *(float4*)a1[i] = *(const float4*)(A1 + (r0+i)*64 + k4);
            *(float4*)a2[i] = *(const float4*)(A2 + (r0+i)*64 + k4);
        }
#pragma unroll
        for (int kk = 0; kk < 4; kk++) {
            *(float4*)b1[kk] = *(const float4*)(B1 + (k4+kk)*64 + c0);
            *(float4*)b2[kk] = *(const float4*)(B2 + (k4+kk)*64 + c0);
        }
#pragma unroll
        for (int kk = 0; kk < 4; kk++)
#pragma unroll
            for (int i = 0; i < 2; i++)
#pragma unroll
                for (int j = 0; j < 4; j++) {
                    acc[i][j] = fmaf(a1[i][kk], b1[kk][j], acc[i][j]);
                    acc[i][j] = fmaf(a2[i][kk], b2[kk][j], acc[i][j]);
                }
    }
}

// ============================================================
// K0a/K0b: used-row flags (deterministic per call)
// ============================================================
__global__ __launch_bounds__(256) void k_zero() {
    int i = blockIdx.x * 256 + threadIdx.x;
    if (i < NI) g_used[i] = 0;
}
__global__ __launch_bounds__(256) void k_mark(const int* __restrict__ logs) {
    int p = blockIdx.x * 256 + threadIdx.x;
    if (p < NP) g_used[logs[p]] = 1;   // racy stores of same value: benign
}

// ============================================================
// K1: tiled  h = emb@W ; wh1/wh2 fused.  grid ceil(NI/64)
// ============================================================
__global__ __launch_bounds__(256) void k_h2(const float* __restrict__ emb,
                                            const float* __restrict__ W,
                                            const float* __restrict__ a) {
    __shared__ float Xs[64*64];
    __shared__ float Ws[64*64];
    int t = threadIdx.x;
    int base = blockIdx.x * 64;
    for (int i = t; i < 1024; i += 256) {
        int row = i >> 4, c4 = (i & 15) * 4;
        float4 v = make_float4(0.f,0.f,0.f,0.f);
        if (base + row < NI) v = *(const float4*)(emb + (base+row)*64 + c4);
        *(float4*)(Xs + row*64 + c4) = v;
        *(float4*)(Ws + i*4) = *(const float4*)(W + i*4);
    }
    __syncthreads();
    int tx = t & 15, ty = t >> 4;
    int r0 = ty*4, c0 = tx*4;
    float acc[4][4] = {};
    gemm_acc(Xs, Ws, acc, r0, c0);

    float4 a1v = *(const float4*)(a + c0);
    float4 a2v = *(const float4*)(a + 64 + c0);
#pragma unroll
    for (int i = 0; i < 4; i++) {
        int gr = base + r0 + i;
        if (gr < NI)
            *(float4*)(g_h + gr*64 + c0) =
                make_float4(acc[i][0], acc[i][1], acc[i][2], acc[i][3]);
        float p1 = acc[i][0]*a1v.x + acc[i][1]*a1v.y + acc[i][2]*a1v.z + acc[i][3]*a1v.w;
        float p2 = acc[i][0]*a2v.x + acc[i][1]*a2v.y + acc[i][2]*a2v.z + acc[i][3]*a2v.w;
#pragma unroll
        for (int o = 8; o > 0; o >>= 1) {
            p1 += __shfl_xor_sync(0xffffffffu, p1, o);
            p2 += __shfl_xor_sync(0xffffffffu, p2, o);
        }
        if (tx == 0 && gr < NI) { g_wh1[gr] = p1; g_wh2[gr] = p2; }
    }
}

// ============================================================
// K2 (fused): skip unused rows; stream+compact, gather+apply.
// Warp per row; grid ceil(NI/8) x 256.
// ============================================================
__device__ __forceinline__ int emit4(float4 v, int colbase, int cnt,
                                     int* cols, float* vals,
                                     int lane, unsigned lt) {
    unsigned mx = __ballot_sync(0xffffffffu, v.x != 0.f);
    unsigned my = __ballot_sync(0xffffffffu, v.y != 0.f);
    unsigned mz = __ballot_sync(0xffffffffu, v.z != 0.f);
    unsigned mw = __ballot_sync(0xffffffffu, v.w != 0.f);
    if ((mx | my | mz | mw) == 0u) return cnt;
    int cx = __popc(mx), cy = __popc(my), cz = __popc(mz), cw = __popc(mw);
    int col = colbase + lane*4;
    if (v.x != 0.f) {
        int w = cnt + __popc(mx & lt);
        if (w < CAP) { cols[w] = col;     vals[w] = v.x; }
    }
    if (v.y != 0.f) {
        int w = cnt + cx + __popc(my & lt);
        if (w < CAP) { cols[w] = col + 1; vals[w] = v.y; }
    }
    if (v.z != 0.f) {
        int w = cnt + cx + cy + __popc(mz & lt);
        if (w < CAP) { cols[w] = col + 2; vals[w] = v.z; }
    }
    if (v.w != 0.f) {
        int w = cnt + cx + cy + cz + __popc(mw & lt);
        if (w < CAP) { cols[w] = col + 3; vals[w] = v.w; }
    }
    return cnt + cx + cy + cz + cw;
}

__device__ __forceinline__ void apply_one(int j, float av, int lane, float w1,
                                          float& t0, float& t1,
                                          float& g0, float& g1, float& den) {
    float hj0 = g_h[j*DD + lane];
    float hj1 = g_h[j*DD + 32 + lane];
    float e = w1 + g_wh2[j];
    e = (e > 0.f) ? e : 0.01f * e;
    float w = __expf(e);
    t0 = fmaf(av, hj0, t0);
    t1 = fmaf(av, hj1, t1);
    g0 = fmaf(w, hj0, g0);
    g1 = fmaf(w, hj1, g1);
    den += w;
}

__global__ __launch_bounds__(256) void k_adjf(const float* __restrict__ adj) {
    __shared__ int   scols[8*CAP];
    __shared__ float svals[8*CAP];
    int warp = threadIdx.x >> 5;
    int lane = threadIdx.x & 31;
    int row  = blockIdx.x * 8 + warp;
    if (row >= NI) return;
    if (!g_used[row]) return;          // warp-uniform skip of unreferenced rows

    unsigned lt = (1u << lane) - 1u;
    int*   cols = scols + warp*CAP;
    float* vals = svals + warp*CAP;
    const float* arow = adj + (long long)row * NI;
    int cnt = 0;

    int p0 = (4 - (row & 3)) & 3;
    {
        float a = (lane < p0) ? arow[lane] : 0.f;
        unsigned m = __ballot_sync(0xffffffffu, a != 0.f);
        if (a != 0.f) {
            int off = __popc(m & lt);
            if (cnt + off < CAP) { cols[cnt+off] = lane; vals[cnt+off] = a; }
        }
        cnt += __popc(m);
    }
    const float4* a4 = (const float4*)(arow + p0);
    int n4 = (NI - p0) >> 2;
    int i = 0;
    for (; i + 128 <= n4; i += 128) {
        float4 v0 = __ldcs(&a4[i       + lane]);
        float4 v1 = __ldcs(&a4[i +  32 + lane]);
        float4 v2 = __ldcs(&a4[i +  64 + lane]);
        float4 v3 = __ldcs(&a4[i +  96 + lane]);
        cnt = emit4(v0, p0 + (i      )*4, cnt, cols, vals, lane, lt);
        cnt = emit4(v1, p0 + (i +  32)*4, cnt, cols, vals, lane, lt);
        cnt = emit4(v2, p0 + (i +  64)*4, cnt, cols, vals, lane, lt);
        cnt = emit4(v3, p0 + (i +  96)*4, cnt, cols, vals, lane, lt);
    }
    for (; i < n4; i += 32) {
        float4 v = (i + lane < n4) ? __ldcs(&a4[i + lane])
                                   : make_float4(0.f,0.f,0.f,0.f);
        cnt = emit4(v, p0 + i*4, cnt, cols, vals, lane, lt);
    }
    int st = p0 + n4*4;
    {
        int j = st + lane;
        float a = (j < NI) ? arow[j] : 0.f;
        unsigned m = __ballot_sync(0xffffffffu, a != 0.f);
        if (a != 0.f) {
            int off = __popc(m & lt);
            if (cnt + off < CAP) { cols[cnt+off] = j; vals[cnt+off] = a; }
        }
        cnt += __popc(m);
    }
    int n = (cnt < CAP) ? cnt : CAP;

    float w1 = g_wh1[row];
    float t0 = 0.f, t1 = 0.f, g0 = 0.f, g1 = 0.f, den = 0.f;
    int k = 0;
    for (; k + 8 <= n; k += 8) {
        int   j0 = cols[k],   j1 = cols[k+1], j2 = cols[k+2], j3 = cols[k+3];
        int   j4 = cols[k+4], j5 = cols[k+5], j6 = cols[k+6], j7 = cols[k+7];
        float a0 = vals[k],   a1 = vals[k+1], a2 = vals[k+2], a3 = vals[k+3];
        float a4v = vals[k+4], a5 = vals[k+5], a6 = vals[k+6], a7 = vals[k+7];
        apply_one(j0, a0, lane, w1, t0, t1, g0, g1, den);
        apply_one(j1, a1, lane, w1, t0, t1, g0, g1, den);
        apply_one(j2, a2, lane, w1, t0, t1, g0, g1, den);
        apply_one(j3, a3, lane, w1, t0, t1, g0, g1, den);
        apply_one(j4, a4v, lane, w1, t0, t1, g0, g1, den);
        apply_one(j5, a5, lane, w1, t0, t1, g0, g1, den);
        apply_one(j6, a6, lane, w1, t0, t1, g0, g1, den);
        apply_one(j7, a7, lane, w1, t0, t1, g0, g1, den);
    }
    for (; k < n; k++) apply_one(cols[k], vals[k], lane, w1, t0, t1, g0, g1, den);

    float inv = 1.f / den;
    g_trans[row*DD + lane]      = t0;
    g_trans[row*DD + 32 + lane] = t1;
    g_gat[row*DD + lane]        = g0 * inv;
    g_gat[row*DD + 32 + lane]   = g1 * inv;
}

// ============================================================
// K3: tiled seq — 32 positions/block, 48KB dyn smem, grid 200.
// ============================================================
__global__ __launch_bounds__(256) void k_seq2(const int* __restrict__ logs,
                                              const float* __restrict__ emb,
                                              const float* __restrict__ posT,
                                              const float* __restrict__ cc,
                                              const float* __restrict__ cn,
                                              const float* __restrict__ W1,
                                              const float* __restrict__ W2) {
    extern __shared__ float sm[];
    float* GR = sm;
    float* TR = sm + 2048;
    float* WA = sm + 4096;
    float* WB = sm + 8192;
    __shared__ int ids[32];

    int t = threadIdx.x;
    int p0 = blockIdx.x * 32;
    if (t < 32) ids[t] = logs[p0 + t];
    for (int i = t; i < 1024; i += 256) {
        *(float4*)(WA + i*4) = *(const float4*)(cc + i*4);
        *(float4*)(WB + i*4) = *(const float4*)(cn + i*4);
    }
    __syncthreads();
    for (int i = t; i < 512; i += 256) {
        int row = i >> 4, c4 = (i & 15) * 4;
        int id = ids[row];
        *(float4*)(GR + row*64 + c4) = *(const float4*)(g_gat + id*64 + c4);
        *(float4*)(TR + row*64 + c4) = *(const float4*)(g_trans + id*64 + c4);
    }
    __syncthreads();

    int tx = t & 15, ty = t >> 4;
    int r0 = ty*2, c0 = tx*4;
    float acc[2][4] = {};
    g24_2A(GR, TR, WA, WB, acc, r0, c0);
    __syncthreads();

    for (int i = t; i < 1024; i += 256) {
        *(float4*)(WA + i*4) = *(const float4*)(W1 + i*4);
        *(float4*)(WB + i*4) = *(const float4*)(W2 + i*4);
    }
#pragma unroll
    for (int i = 0; i < 2; i++) {
        int r = r0 + i;
        int id = ids[r];
        int p  = p0 + r;
        int l  = p % LL;
        float4 gv = *(float4*)(GR + r*64 + c0);
        float4 tv = *(float4*)(TR + r*64 + c0);
        float4 ev = *(const float4*)(emb + id*64 + c0);
        float4 pv = make_float4(0.f,0.f,0.f,0.f);
        if (id != 0) pv = *(const float4*)(posT + l*64 + c0);
        float s0 = tv.x + ev.x, s1 = tv.y + ev.y, s2 = tv.z + ev.z, s3 = tv.w + ev.w;
        float c0f = __fdividef(1.f, 1.f + __expf(-acc[i][0]));
        float c1f = __fdividef(1.f, 1.f + __expf(-acc[i][1]));
        float c2f = __fdividef(1.f, 1.f + __expf(-acc[i][2]));
        float c3f = __fdividef(1.f, 1.f + __expf(-acc[i][3]));
        s0 = fmaf(c0f, gv.x - tv.x, s0);
        s1 = fmaf(c1f, gv.y - tv.y, s1);
        s2 = fmaf(c2f, gv.z - tv.z, s2);
        s3 = fmaf(c3f, gv.w - tv.w, s3);
        *(float4*)(g_seqs + p*64 + c0) = make_float4(s0, s1, s2, s3);
        *(float4*)(GR + r*64 + c0) =
            make_float4(s0 + pv.x, s1 + pv.y, s2 + pv.z, s3 + pv.w);
    }
    __syncthreads();

    float m1[2][4] = {}, m2[2][4] = {};
    g24_2B(GR, WA, WB, m1, m2, r0, c0);
#pragma unroll
    for (int i = 0; i < 2; i++) {
        int p = p0 + r0 + i;
        *(float4*)(g_M1 + p*64 + c0) =
            make_float4(0.5f*m1[i][0], 0.5f*m1[i][1], 0.5f*m1[i][2], 0.5f*m1[i][3]);
        *(float4*)(g_M2 + p*64 + c0) =
            make_float4(0.5f*m2[i][0], 0.5f*m2[i][1], 0.5f*m2[i][2], 0.5f*m2[i][3]);
    }
}

// ============================================================
// K4a: score tiles — one block per causal 32x32 tile.
// ============================================================
__global__ __launch_bounds__(256) void k_score(const float* __restrict__ battn) {
    int b   = blockIdx.y;
    int tid = blockIdx.x;
    int qt = 0, base = 0;
    while (base + qt + 1 <= tid) { base += qt + 1; qt++; }
    int kt = tid - base;
    int t = threadIdx.x;

    __shared__ float m1s[32*68];
    __shared__ float m2s[32*64];
    __shared__ float bs2[64];

    for (int i = t; i < 512; i += 256) {
        int row = i >> 4, c4 = (i & 15)*4;
        int qg = qt*QT + row;
        float4 v = (qg < LL) ? *(const float4*)(g_M1 + (b*LL+qg)*64 + c4)
                             : make_float4(0.f,0.f,0.f,0.f);
        *(float4*)(m1s + row*68 + c4) = v;
        int kg = kt*KT + row;
        float4 w = (kg < LL) ? *(const float4*)(g_M2 + (b*LL+kg)*64 + c4)
                             : make_float4(0.f,0.f,0.f,0.f);
        *(float4*)(m2s + row*64 + c4) = w;
    }
    if (t < 64) bs2[t] = 0.5f * battn[t];
    __syncthreads();

    int ql = t & 31;
    int kb = (t >> 5) << 2;
    int qg = qt*QT + ql;

    float hs = 0.f;
#pragma unroll
    for (int d = 0; d < 64; d += 4) {
        float4 bv = *(float4*)(bs2 + d);
        hs += bv.x + bv.y + bv.z + bv.w;
    }

    float s0 = 0.f, s1 = 0.f, s2 = 0.f, s3 = 0.f;
#pragma unroll 4
    for (int d4 = 0; d4 < 64; d4 += 4) {
        float4 m1v = *(float4*)(m1s + ql*68 + d4);
        float4 b2  = *(float4*)(bs2 + d4);
        float4 k0  = *(float4*)(m2s + (kb+0)*64 + d4);
        float4 k1  = *(float4*)(m2s + (kb+1)*64 + d4);
        float4 k2  = *(float4*)(m2s + (kb+2)*64 + d4);
        float4 k3  = *(float4*)(m2s + (kb+3)*64 + d4);
        s0 = fmaf(b2.x, tanha(m1v.x + k0.x), s0);
        s1 = fmaf(b2.x, tanha(m1v.x + k1.x), s1);
        s2 = fmaf(b2.x, tanha(m1v.x + k2.x), s2);
        s3 = fmaf(b2.x, tanha(m1v.x + k3.x), s3);
        s0 = fmaf(b2.y, tanha(m1v.y + k0.y), s0);
        s1 = fmaf(b2.y, tanha(m1v.y + k1.y), s1);
        s2 = fmaf(b2.y, tanha(m1v.y + k2.y), s2);
        s3 = fmaf(b2.y, tanha(m1v.y + k3.y), s3);
        s0 = fmaf(b2.z, tanha(m1v.z + k0.z), s0);
        s1 = fmaf(b2.z, tanha(m1v.z + k1.z), s1);
        s2 = fmaf(b2.z, tanha(m1v.z + k2.z), s2);
        s3 = fmaf(b2.z, tanha(m1v.z + k3.z), s3);
        s0 = fmaf(b2.w, tanha(m1v.w + k0.w), s0);
        s1 = fmaf(b2.w, tanha(m1v.w + k1.w), s1);
        s2 = fmaf(b2.w, tanha(m1v.w + k2.w), s2);
        s3 = fmaf(b2.w, tanha(m1v.w + k3.w), s3);
    }
    if (qg < LL) {
        int kg0 = kt*KT + kb;
        float* srow = &g_score[((long long)b*LL + qg)*LL];
        if (kg0+0 < LL) srow[kg0+0] = (kg0+0 <= qg) ? s0 + hs : 0.f;
        if (kg0+1 < LL) srow[kg0+1] = (kg0+1 <= qg) ? s1 + hs : 0.f;
        if (kg0+2 < LL) srow[kg0+2] = (kg0+2 <= qg) ? s2 + hs : 0.f;
        if (kg0+3 < LL) srow[kg0+3] = (kg0+3 <= qg) ? s3 + hs : 0.f;
    }
}

// ============================================================
// K5 (balanced fused): block = (pair of q-tiles {6-2p, 5-2p}, b).
// ============================================================
__global__ __launch_bounds__(256) void k_ffn4(const int* __restrict__ pos_s,
                                              const int* __restrict__ neg_s,
                                              const float* __restrict__ emb,
                                              const float* __restrict__ c1w,
                                              const float* __restrict__ c1b,
                                              const float* __restrict__ c2w,
                                              const float* __restrict__ c2b,
                                              const float* __restrict__ upw,
                                              const float* __restrict__ upb,
                                              const float* __restrict__ gw,
                                              const float* __restrict__ gb,
                                              const float* __restrict__ dw,
                                              const float* __restrict__ db,
                                              float* __restrict__ out) {
    extern __shared__ float sm[];
    float* F0 = sm;
    float* R1 = sm + 4096;
    float* F2 = sm + 8192;
    float* WA = sm + 12288;
    float* WB = sm + 16384;
    float* GU = sm;
    float* seqss = WA;
    float* scsA  = WB;
    float* scsB  = WB + 1152;

    int t = threadIdx.x;
    int b = blockIdx.y;
    int p = blockIdx.x;
    int qtA = 6 - 2*p;
    int qtB = qtA - 1;

    int qrow  = t >> 3;
    int dbase = (t & 7) << 3;
    float accA[8], accB[8];
#pragma unroll
    for (int i = 0; i < 8; i++) { accA[i] = 0.f; accB[i] = 0.f; }

    for (int kt = 0; kt <= qtA; kt++) {
        __syncthreads();
        for (int i = t; i < 512; i += 256) {
            int kl = i >> 4, c4 = (i & 15) * 4;
            int kg = kt*KT + kl;
            float4 v = (kg < LL) ? *(const float4*)(g_seqs + (b*LL+kg)*64 + c4)
                                 : make_float4(0.f,0.f,0.f,0.f);
            *(float4*)(seqss + kl*64 + c4) = v;
        }
        {
            int ql = t >> 3, c4 = (t & 7) * 4;
            int kg = kt*KT + c4;
            int qgA = qtA*QT + ql;
            float4 v = (qgA < LL && kg < LL)
                     ? *(const float4*)(g_score + ((long long)b*LL + qgA)*LL + kg)
                     : make_float4(0.f,0.f,0.f,0.f);
            *(float4*)(scsA + ql*36 + c4) = v;
            float4 w = make_float4(0.f,0.f,0.f,0.f);
            if (qtB >= 0 && kg < LL) {
                int qgB = qtB*QT + ql;
                w = *(const float4*)(g_score + ((long long)b*LL + qgB)*LL + kg);
            }
            *(float4*)(scsB + ql*36 + c4) = w;
        }
        __syncthreads();
#pragma unroll 4
        for (int k = 0; k < KT; k++) {
            float svA = scsA[qrow*36 + k];
            float svB = scsB[qrow*36 + k];
            float4 v0 = *(float4*)(seqss + k*64 + dbase);
            float4 v1 = *(float4*)(seqss + k*64 + dbase + 4);
            accA[0] = fmaf(svA, v0.x, accA[0]);
            accA[1] = fmaf(svA, v0.y, accA[1]);
            accA[2] = fmaf(svA, v0.z, accA[2]);
            accA[3] = fmaf(svA, v0.w, accA[3]);
            accA[4] = fmaf(svA, v1.x, accA[4]);
            accA[5] = fmaf(svA, v1.y, accA[5]);
            accA[6] = fmaf(svA, v1.z, accA[6]);
            accA[7] = fmaf(svA, v1.w, accA[7]);
            accB[0] = fmaf(svB, v0.x, accB[0]);
            accB[1] = fmaf(svB, v0.y, accB[1]);
            accB[2] = fmaf(svB, v0.z, accB[2]);
            accB[3] = fmaf(svB, v0.w, accB[3]);
            accB[4] = fmaf(svB, v1.x, accB[4]);
            accB[5] = fmaf(svB, v1.y, accB[5]);
            accB[6] = fmaf(svB, v1.z, accB[6]);
            accB[7] = fmaf(svB, v1.w, accB[7]);
        }
    }
    __syncthreads();
    *(float4*)(F0 + qrow*64 + dbase)          = make_float4(accA[0], accA[1], accA[2], accA[3]);
    *(float4*)(F0 + qrow*64 + dbase + 4)      = make_float4(accA[4], accA[5], accA[6], accA[7]);
    *(float4*)(F0 + (32+qrow)*64 + dbase)     = make_float4(accB[0], accB[1], accB[2], accB[3]);
    *(float4*)(F0 + (32+qrow)*64 + dbase + 4) = make_float4(accB[4], accB[5], accB[6], accB[7]);
    __syncthreads();

    int tx = t & 15, ty = t >> 4;
    int r0 = ty*4, c0 = tx*4;

    for (int i = t; i < 1024; i += 256) {
        *(float4*)(WA + i*4) = *(const float4*)(c1w + i*4);
        *(float4*)(WB + i*4) = *(const float4*)(c2w + i*4);
    }
    __syncthreads();

    {
        float a2[4][4] = {};
        gemm_acc(F0, WA, a2, r0, c0);
        float4 bv = *(const float4*)(c1b + c0);
#pragma unroll
        for (int i = 0; i < 4; i++)
            *(float4*)(R1 + (r0+i)*64 + c0) = make_float4(
                fmaxf(a2[i][0] + bv.x, 0.f), fmaxf(a2[i][1] + bv.y, 0.f),
                fmaxf(a2[i][2] + bv.z, 0.f), fmaxf(a2[i][3] + bv.w, 0.f));
    }
    __syncthreads();

    {
        float a2[4][4] = {};
        gemm_acc(R1, WB, a2, r0, c0);
        float4 bv = *(const float4*)(c2b + c0);
#pragma unroll
        for (int i = 0; i < 4; i++) {
            float4 f0v = *(float4*)(F0 + (r0+i)*64 + c0);
            *(float4*)(F2 + (r0+i)*64 + c0) = make_float4(
                f0v.x + a2[i][0] + bv.x, f0v.y + a2[i][1] + bv.y,
                f0v.z + a2[i][2] + bv.z, f0v.w + a2[i][3] + bv.w);
        }
    }
    __syncthreads();

#pragma unroll
    for (int half = 0; half < 2; half++) {
        for (int i = t; i < 1024; i += 256) {
            int row = i >> 4, c4 = (i & 15) * 4;
            *(float4*)(WA + row*64 + c4) = *(const float4*)(upw + row*128 + half*64 + c4);
            *(float4*)(WB + row*64 + c4) = *(const float4*)(gw  + row*128 + half*64 + c4);
        }
        __syncthreads();
        float au[4][4] = {}, ag[4][4] = {};
        gemm_acc2B4(F2, WA, WB, au, ag, r0, c0);
        float4 ub  = *(const float4*)(upb + half*64 + c0);
        float4 gb4 = *(const float4*)(gb + half*64 + c0);
#pragma unroll
        for (int i = 0; i < 4; i++) {
            float g0v = fmaxf(ag[i][0] + gb4.x, 0.f) * (au[i][0] + ub.x);
            float g1v = fmaxf(ag[i][1] + gb4.y, 0.f) * (au[i][1] + ub.y);
            float g2v = fmaxf(ag[i][2] + gb4.z, 0.f) * (au[i][2] + ub.z);
            float g3v = fmaxf(ag[i][3] + gb4.w, 0.f) * (au[i][3] + ub.w);
            *(float4*)(GU + (r0+i)*128 + half*64 + c0) = make_float4(g0v, g1v, g2v, g3v);
        }
        __syncthreads();
    }

    for (int i = t; i < 1024; i += 256) {
        *(float4*)(WA + i*4) = *(const float4*)(dw + i*4);
        *(float4*)(WB + i*4) = *(const float4*)(dw + 4096 + i*4);
    }
    __syncthreads();
    float fo[4][4];
    {
        float a2[4][4] = {};
#pragma unroll 4
        for (int k4 = 0; k4 < 128; k4 += 4) {
            const float* Bsrc = (k4 < 64) ? (WA + k4*64) : (WB + (k4-64)*64);
            float aa[4][4], bb[4][4];
#pragma unroll
            for (int i = 0; i < 4; i++)
                *(float4*)aa[i] = *(const float4*)(GU + (r0+i)*128 + k4);
#pragma unroll
            for (int kk = 0; kk < 4; kk++)
                *(float4*)bb[kk] = *(const float4*)(Bsrc + kk*64 + c0);
#pragma unroll
            for (int kk = 0; kk < 4; kk++)
#pragma unroll
                for (int i = 0; i < 4; i++)
#pragma unroll
                    for (int j = 0; j < 4; j++)
                        a2[i][j] = fmaf(aa[i][kk], bb[kk][j], a2[i][j]);
        }
        float4 bv = *(const float4*)(db + c0);
#pragma unroll
        for (int i = 0; i < 4; i++) {
            float4 f2v = *(float4*)(F2 + (r0+i)*64 + c0);
            fo[i][0] = f2v.x + fmaxf(a2[i][0] + bv.x, 0.f);
            fo[i][1] = f2v.y + fmaxf(a2[i][1] + bv.y, 0.f);
            fo[i][2] = f2v.z + fmaxf(a2[i][2] + bv.z, 0.f);
            fo[i][3] = f2v.w + fmaxf(a2[i][3] + bv.w, 0.f);
        }
    }
    __syncthreads();
#pragma unroll
    for (int i = 0; i < 4; i++)
        *(float4*)(WA + (r0+i)*64 + c0) =
            make_float4(fo[i][0], fo[i][1], fo[i][2], fo[i][3]);
    __syncthreads();

    {
        int r  = t >> 2;
        int q  = t & 3;
        int d0 = q * 16;
        int qg = (r < 32) ? (qtA*QT + r)
                          : ((qtB >= 0) ? (qtB*QT + r - 32) : LL);
        if (qg < LL) {
            int gp = b*LL + qg;
            int ip = pos_s[gp], in_ = neg_s[gp];
            float pl = 0.f, nl = 0.f;
#pragma unroll
            for (int d = 0; d < 16; d += 4) {
                float4 f  = *(float4*)(WA + r*64 + d0 + d);
                float4 ep = *(const float4*)(emb + ip*64 + d0 + d);
                float4 en = *(const float4*)(emb + in_*64 + d0 + d);
                pl += f.x*ep.x + f.y*ep.y + f.z*ep.z + f.w*ep.w;
                nl += f.x*en.x + f.y*en.y + f.z*en.z + f.w*en.w;
            }
            pl += __shfl_xor_sync(0xffffffffu, pl, 1);
            pl += __shfl_xor_sync(0xffffffffu, pl, 2);
            nl += __shfl_xor_sync(0xffffffffu, nl, 1);
            nl += __shfl_xor_sync(0xffffffffu, nl, 2);
            if (q == 0) { out[gp] = pl; out[NP + gp] = nl; }
        }
    }
}

// ============================================================
extern "C" void kernel_launch(void* const* d_in, const int* in_sizes, int n_in,
                              void* d_out, int out_size) {
    const int*   log_seqs = (const int*)  d_in[0];
    const int*   pos_seqs = (const int*)  d_in[1];
    const int*   neg_seqs = (const int*)  d_in[2];
    const float* adj      = (const float*)d_in[4];
    const float* item_emb = (const float*)d_in[5];
    const float* pos_emb  = (const float*)d_in[6];
    const float* W_item   = (const float*)d_in[7];
    const float* a_item   = (const float*)d_in[8];
    const float* W_1      = (const float*)d_in[9];
    const float* W_2      = (const float*)d_in[10];
    const float* b_attn   = (const float*)d_in[11];
    const float* co_c     = (const float*)d_in[12];
    const float* co_n     = (const float*)d_in[13];
    const float* c1w      = (const float*)d_in[14];
    const float* c1b      = (const float*)d_in[15];
    const float* c2w      = (const float*)d_in[16];
    const float* c2b      = (const float*)d_in[17];
    const float* upw      = (const float*)d_in[18];
    const float* upb      = (const float*)d_in[19];
    const float* gw       = (const float*)d_in[20];
    const float* gb       = (const float*)d_in[21];
    const float* dw       = (const float*)d_in[22];
    const float* db       = (const float*)d_in[23];
    float* out = (float*)d_out;

    static bool attr_done = false;
    if (!attr_done) {
        cudaFuncSetAttribute(k_seq2, cudaFuncAttributeMaxDynamicSharedMemorySize, 49152);
        cudaFuncSetAttribute(k_ffn4, cudaFuncAttributeMaxDynamicSharedMemorySize, 81920);
        attr_done = true;
    }

    k_zero <<<(NI + 255) / 256, 256>>>();
    k_mark <<<(NP + 255) / 256, 256>>>(log_seqs);
    k_h2   <<<(NI + 63) / 64, 256>>>(item_emb, W_item, a_item);
    k_adjf <<<(NI + 7) / 8, 256>>>(adj);
    k_seq2 <<<NP / 32, 256, 49152>>>(log_seqs, item_emb, pos_emb,
                                     co_c, co_n, W_1, W_2);
    dim3 sg(28, BB);
    k_score<<<sg, 256>>>(b_attn);
    dim3 fg(4, BB);
    k_ffn4 <<<fg, 256, 81920>>>(pos_seqs, neg_seqs, item_emb,
                                c1w, c1b, c2w, c2b, upw, upb,
                                gw, gb, dw, db, out);
}

// round 11
// speedup vs baseline: 1.2409x; 1.0313x over previous
#include <cuda_runtime.h>

#define NI   6001
#define DD   64
#define LL   200
#define BB   32
#define NP   (BB*LL)   // 6400 positions
#define QT   32
#define KT   32
#define CAP  192       // max nonzeros per adj row

// ---- device scratch (no allocations allowed) ----
__device__ float g_h[NI*DD];
__device__ float g_wh1[NI];
__device__ float g_wh2[NI];
__device__ float g_trans[NI*DD];
__device__ float g_gat[NI*DD];
__device__ float g_seqs[NP*DD];
__device__ float g_M1[NP*DD];
__device__ float g_M2[NP*DD];
__device__ float g_score[BB*LL*LL];
__device__ int   g_used[NI];
__device__ int   g_rowlist[NI];
__device__ int   g_nrows;

__device__ __forceinline__ float tanha(float x) {
    float t;
    asm("tanh.approx.f32 %0, %1;" : "=f"(t) : "f"(x));
    return t;
}

// ---- 4x4-tile GEMM helper (64-row blocks) ----
__device__ __forceinline__ void gemm_acc(const float* __restrict__ A,
                                         const float* __restrict__ B,
                                         float acc[4][4], int r0, int c0) {
#pragma unroll 4
    for (int k4 = 0; k4 < 64; k4 += 4) {
        float aa[4][4], bb[4][4];
#pragma unroll
        for (int i = 0; i < 4; i++)
            *(float4*)aa[i] = *(const float4*)(A + (r0+i)*64 + k4);
#pragma unroll
        for (int kk = 0; kk < 4; kk++)
            *(float4*)bb[kk] = *(const float4*)(B + (k4+kk)*64 + c0);
#pragma unroll
        for (int kk = 0; kk < 4; kk++)
#pragma unroll
            for (int i = 0; i < 4; i++)
#pragma unroll
                for (int j = 0; j < 4; j++)
                    acc[i][j] = fmaf(aa[i][kk], bb[kk][j], acc[i][j]);
    }
}

__device__ __forceinline__ void gemm_acc2B4(const float* __restrict__ A,
                                            const float* __restrict__ B1,
                                            const float* __restrict__ B2,
                                            float accP[4][4], float accQ[4][4],
                                            int r0, int c0) {
#pragma unroll 4
    for (int k4 = 0; k4 < 64; k4 += 4) {
        float aa[4][4], b1[4][4], b2[4][4];
#pragma unroll
        for (int i = 0; i < 4; i++)
            *(float4*)aa[i] = *(const float4*)(A + (r0+i)*64 + k4);
#pragma unroll
        for (int kk = 0; kk < 4; kk++) {
            *(float4*)b1[kk] = *(const float4*)(B1 + (k4+kk)*64 + c0);
            *(float4*)b2[kk] = *(const float4*)(B2 + (k4+kk)*64 + c0);
        }
#pragma unroll
        for (int kk = 0; kk < 4; kk++)
#pragma unroll
            for (int i = 0; i < 4; i++)
#pragma unroll
                for (int j = 0; j < 4; j++) {
                    accP[i][j] = fmaf(aa[i][kk], b1[kk][j], accP[i][j]);
                    accQ[i][j] = fmaf(aa[i][kk], b2[kk][j], accQ[i][j]);
                }
    }
}

// ---- 2x4-tile GEMM helpers (32-row blocks) ----
__device__ __forceinline__ void g24_2B(const float* __restrict__ A,
                                       const float* __restrict__ B1,
                                       const float* __restrict__ B2,
                                       float accP[2][4], float accQ[2][4],
                                       int r0, int c0) {
#pragma unroll 4
    for (int k4 = 0; k4 < 64; k4 += 4) {
        float aa[2][4], b1[4][4], b2[4][4];
#pragma unroll
        for (int i = 0; i < 2; i++)
            *(float4*)aa[i] = *(const float4*)(A + (r0+i)*64 + k4);
#pragma unroll
        for (int kk = 0; kk < 4; kk++) {
            *(float4*)b1[kk] = *(const float4*)(B1 + (k4+kk)*64 + c0);
            *(float4*)b2[kk] = *(const float4*)(B2 + (k4+kk)*64 + c0);
        }
#pragma unroll
        for (int kk = 0; kk < 4; kk++)
#pragma unroll
            for (int i = 0; i < 2; i++)
#pragma unroll
                for (int j = 0; j < 4; j++) {
                    accP[i][j] = fmaf(aa[i][kk], b1[kk][j], accP[i][j]);
                    accQ[i][j] = fmaf(aa[i][kk], b2[kk][j], accQ[i][j]);
                }
    }
}

__device__ __forceinline__ void g24_2A(const float* __restrict__ A1,
                                       const float* __restrict__ A2,
                                       const float* __restrict__ B1,
                                       const float* __restrict__ B2,
                                       float acc[2][4], int r0, int c0) {
#pragma unroll 4
    for (int k4 = 0; k4 < 64; k4 += 4) {
        float a1[2][4], a2[2][4], b1[4][4], b2[4][4];
#pragma unroll
        for (int i = 0; i < 2; i++) {
            *(float4*)a1[i] = *(const float4*)(A1 + (r0+i)*64 + k4);
            *(float4*)a2[i] = *(const float4*)(A2 + (r0+i)*64 + k4);
        }
#pragma unroll
        for (int kk = 0; kk < 4; kk++) {
            *(float4*)b1[kk] = *(const float4*)(B1 + (k4+kk)*64 + c0);
            *(float4*)b2[kk] = *(const float4*)(B2 + (k4+kk)*64 + c0);
        }
#pragma unroll
        for (int kk = 0; kk < 4; kk++)
#pragma unroll
            for (int i = 0; i < 2; i++)
#pragma unroll
                for (int j = 0; j < 4; j++) {
                    acc[i][j] = fmaf(a1[i][kk], b1[kk][j], acc[i][j]);
                    acc[i][j] = fmaf(a2[i][kk], b2[kk][j], acc[i][j]);
                }
    }
}

// ============================================================
// K0a/K0b: build dense used-row list (order nondeterministic;
// per-row outputs independent => replay-deterministic results)
// ============================================================
__global__ __launch_bounds__(256) void k_zero() {
    int i = blockIdx.x * 256 + threadIdx.x;
    if (i < NI) g_used[i] = 0;
    if (i == 0) g_nrows = 0;
}
__global__ __launch_bounds__(256) void k_mark(const int* __restrict__ logs) {
    int p = blockIdx.x * 256 + threadIdx.x;
    if (p < NP) {
        int id = logs[p];
        if (atomicExch(&g_used[id], 1) == 0) {
            int pos = atomicAdd(&g_nrows, 1);
            g_rowlist[pos] = id;
        }
    }
}

// ============================================================
// K1: tiled  h = emb@W ; wh1/wh2 fused.  grid ceil(NI/64)
// ============================================================
__global__ __launch_bounds__(256) void k_h2(const float* __restrict__ emb,
                                            const float* __restrict__ W,
                                            const float* __restrict__ a) {
    __shared__ float Xs[64*64];
    __shared__ float Ws[64*64];
    int t = threadIdx.x;
    int base = blockIdx.x * 64;
    for (int i = t; i < 1024; i += 256) {
        int row = i >> 4, c4 = (i & 15) * 4;
        float4 v = make_float4(0.f,0.f,0.f,0.f);
        if (base + row < NI) v = *(const float4*)(emb + (base+row)*64 + c4);
        *(float4*)(Xs + row*64 + c4) = v;
        *(float4*)(Ws + i*4) = *(const float4*)(W + i*4);
    }
    __syncthreads();
    int tx = t & 15, ty = t >> 4;
    int r0 = ty*4, c0 = tx*4;
    float acc[4][4] = {};
    gemm_acc(Xs, Ws, acc, r0, c0);

    float4 a1v = *(const float4*)(a + c0);
    float4 a2v = *(const float4*)(a + 64 + c0);
#pragma unroll
    for (int i = 0; i < 4; i++) {
        int gr = base + r0 + i;
        if (gr < NI)
            *(float4*)(g_h + gr*64 + c0) =
                make_float4(acc[i][0], acc[i][1], acc[i][2], acc[i][3]);
        float p1 = acc[i][0]*a1v.x + acc[i][1]*a1v.y + acc[i][2]*a1v.z + acc[i][3]*a1v.w;
        float p2 = acc[i][0]*a2v.x + acc[i][1]*a2v.y + acc[i][2]*a2v.z + acc[i][3]*a2v.w;
#pragma unroll
        for (int o = 8; o > 0; o >>= 1) {
            p1 += __shfl_xor_sync(0xffffffffu, p1, o);
            p2 += __shfl_xor_sync(0xffffffffu, p2, o);
        }
        if (tx == 0 && gr < NI) { g_wh1[gr] = p1; g_wh2[gr] = p2; }
    }
}

// ============================================================
// K2 (fused): dense row list; stream+compact, gather+apply.
// Warp per listed row; grid ceil(NI/8) x 256 (excess warps exit).
// ============================================================
__device__ __forceinline__ int emit4(float4 v, int colbase, int cnt,
                                     int* cols, float* vals,
                                     int lane, unsigned lt) {
    unsigned mx = __ballot_sync(0xffffffffu, v.x != 0.f);
    unsigned my = __ballot_sync(0xffffffffu, v.y != 0.f);
    unsigned mz = __ballot_sync(0xffffffffu, v.z != 0.f);
    unsigned mw = __ballot_sync(0xffffffffu, v.w != 0.f);
    if ((mx | my | mz | mw) == 0u) return cnt;
    int cx = __popc(mx), cy = __popc(my), cz = __popc(mz), cw = __popc(mw);
    int col = colbase + lane*4;
    if (v.x != 0.f) {
        int w = cnt + __popc(mx & lt);
        if (w < CAP) { cols[w] = col;     vals[w] = v.x; }
    }
    if (v.y != 0.f) {
        int w = cnt + cx + __popc(my & lt);
        if (w < CAP) { cols[w] = col + 1; vals[w] = v.y; }
    }
    if (v.z != 0.f) {
        int w = cnt + cx + cy + __popc(mz & lt);
        if (w < CAP) { cols[w] = col + 2; vals[w] = v.z; }
    }
    if (v.w != 0.f) {
        int w = cnt + cx + cy + cz + __popc(mw & lt);
        if (w < CAP) { cols[w] = col + 3; vals[w] = v.w; }
    }
    return cnt + cx + cy + cz + cw;
}

__device__ __forceinline__ void apply_one(int j, float av, int lane, float w1,
                                          float& t0, float& t1,
                                          float& g0, float& g1, float& den) {
    float hj0 = g_h[j*DD + lane];
    float hj1 = g_h[j*DD + 32 + lane];
    float e = w1 + g_wh2[j];
    e = (e > 0.f) ? e : 0.01f * e;
    float w = __expf(e);
    t0 = fmaf(av, hj0, t0);
    t1 = fmaf(av, hj1, t1);
    g0 = fmaf(w, hj0, g0);
    g1 = fmaf(w, hj1, g1);
    den += w;
}

__global__ __launch_bounds__(256) void k_adjf(const float* __restrict__ adj) {
    __shared__ int   scols[8*CAP];
    __shared__ float svals[8*CAP];
    int warp = threadIdx.x >> 5;
    int lane = threadIdx.x & 31;
    int gw_  = blockIdx.x * 8 + warp;
    if (gw_ >= g_nrows) return;        // dense list: only trailing warps exit
    int row = g_rowlist[gw_];

    unsigned lt = (1u << lane) - 1u;
    int*   cols = scols + warp*CAP;
    float* vals = svals + warp*CAP;
    const float* arow = adj + (long long)row * NI;
    int cnt = 0;

    int p0 = (4 - (row & 3)) & 3;
    {
        float a = (lane < p0) ? arow[lane] : 0.f;
        unsigned m = __ballot_sync(0xffffffffu, a != 0.f);
        if (a != 0.f) {
            int off = __popc(m & lt);
            if (cnt + off < CAP) { cols[cnt+off] = lane; vals[cnt+off] = a; }
        }
        cnt += __popc(m);
    }
    const float4* a4 = (const float4*)(arow + p0);
    int n4 = (NI - p0) >> 2;
    int i = 0;
    // 8-chunk main loop: 4KB in flight per warp
    for (; i + 256 <= n4; i += 256) {
        float4 v0 = __ldcs(&a4[i        + lane]);
        float4 v1 = __ldcs(&a4[i +  32  + lane]);
        float4 v2 = __ldcs(&a4[i +  64  + lane]);
        float4 v3 = __ldcs(&a4[i +  96  + lane]);
        float4 v4 = __ldcs(&a4[i + 128  + lane]);
        float4 v5 = __ldcs(&a4[i + 160  + lane]);
        float4 v6 = __ldcs(&a4[i + 192  + lane]);
        float4 v7 = __ldcs(&a4[i + 224  + lane]);
        cnt = emit4(v0, p0 + (i       )*4, cnt, cols, vals, lane, lt);
        cnt = emit4(v1, p0 + (i +  32 )*4, cnt, cols, vals, lane, lt);
        cnt = emit4(v2, p0 + (i +  64 )*4, cnt, cols, vals, lane, lt);
        cnt = emit4(v3, p0 + (i +  96 )*4, cnt, cols, vals, lane, lt);
        cnt = emit4(v4, p0 + (i + 128 )*4, cnt, cols, vals, lane, lt);
        cnt = emit4(v5, p0 + (i + 160 )*4, cnt, cols, vals, lane, lt);
        cnt = emit4(v6, p0 + (i + 192 )*4, cnt, cols, vals, lane, lt);
        cnt = emit4(v7, p0 + (i + 224 )*4, cnt, cols, vals, lane, lt);
    }
    for (; i + 128 <= n4; i += 128) {
        float4 v0 = __ldcs(&a4[i       + lane]);
        float4 v1 = __ldcs(&a4[i +  32 + lane]);
        float4 v2 = __ldcs(&a4[i +  64 + lane]);
        float4 v3 = __ldcs(&a4[i +  96 + lane]);
        cnt = emit4(v0, p0 + (i      )*4, cnt, cols, vals, lane, lt);
        cnt = emit4(v1, p0 + (i +  32)*4, cnt, cols, vals, lane, lt);
        cnt = emit4(v2, p0 + (i +  64)*4, cnt, cols, vals, lane, lt);
        cnt = emit4(v3, p0 + (i +  96)*4, cnt, cols, vals, lane, lt);
    }
    for (; i < n4; i += 32) {
        float4 v = (i + lane < n4) ? __ldcs(&a4[i + lane])
                                   : make_float4(0.f,0.f,0.f,0.f);
        cnt = emit4(v, p0 + i*4, cnt, cols, vals, lane, lt);
    }
    int st = p0 + n4*4;
    {
        int j = st + lane;
        float a = (j < NI) ? arow[j] : 0.f;
        unsigned m = __ballot_sync(0xffffffffu, a != 0.f);
        if (a != 0.f) {
            int off = __popc(m & lt);
            if (cnt + off < CAP) { cols[cnt+off] = j; vals[cnt+off] = a; }
        }
        cnt += __popc(m);
    }
    int n = (cnt < CAP) ? cnt : CAP;

    float w1 = g_wh1[row];
    float t0 = 0.f, t1 = 0.f, g0 = 0.f, g1 = 0.f, den = 0.f;
    int k = 0;
    for (; k + 8 <= n; k += 8) {
        int   j0 = cols[k],   j1 = cols[k+1], j2 = cols[k+2], j3 = cols[k+3];
        int   j4 = cols[k+4], j5 = cols[k+5], j6 = cols[k+6], j7 = cols[k+7];
        float a0 = vals[k],   a1 = vals[k+1], a2 = vals[k+2], a3 = vals[k+3];
        float a4v = vals[k+4], a5 = vals[k+5], a6 = vals[k+6], a7 = vals[k+7];
        apply_one(j0, a0, lane, w1, t0, t1, g0, g1, den);
        apply_one(j1, a1, lane, w1, t0, t1, g0, g1, den);
        apply_one(j2, a2, lane, w1, t0, t1, g0, g1, den);
        apply_one(j3, a3, lane, w1, t0, t1, g0, g1, den);
        apply_one(j4, a4v, lane, w1, t0, t1, g0, g1, den);
        apply_one(j5, a5, lane, w1, t0, t1, g0, g1, den);
        apply_one(j6, a6, lane, w1, t0, t1, g0, g1, den);
        apply_one(j7, a7, lane, w1, t0, t1, g0, g1, den);
    }
    for (; k < n; k++) apply_one(cols[k], vals[k], lane, w1, t0, t1, g0, g1, den);

    float inv = 1.f / den;
    g_trans[row*DD + lane]      = t0;
    g_trans[row*DD + 32 + lane] = t1;
    g_gat[row*DD + lane]        = g0 * inv;
    g_gat[row*DD + 32 + lane]   = g1 * inv;
}

// ============================================================
// K3: tiled seq — 32 positions/block, 48KB dyn smem, grid 200.
// ============================================================
__global__ __launch_bounds__(256) void k_seq2(const int* __restrict__ logs,
                                              const float* __restrict__ emb,
                                              const float* __restrict__ posT,
                                              const float* __restrict__ cc,
                                              const float* __restrict__ cn,
                                              const float* __restrict__ W1,
                                              const float* __restrict__ W2) {
    extern __shared__ float sm[];
    float* GR = sm;
    float* TR = sm + 2048;
    float* WA = sm + 4096;
    float* WB = sm + 8192;
    __shared__ int ids[32];

    int t = threadIdx.x;
    int p0 = blockIdx.x * 32;
    if (t < 32) ids[t] = logs[p0 + t];
    for (int i = t; i < 1024; i += 256) {
        *(float4*)(WA + i*4) = *(const float4*)(cc + i*4);
        *(float4*)(WB + i*4) = *(const float4*)(cn + i*4);
    }
    __syncthreads();
    for (int i = t; i < 512; i += 256) {
        int row = i >> 4, c4 = (i & 15) * 4;
        int id = ids[row];
        *(float4*)(GR + row*64 + c4) = *(const float4*)(g_gat + id*64 + c4);
        *(float4*)(TR + row*64 + c4) = *(const float4*)(g_trans + id*64 + c4);
    }
    __syncthreads();

    int tx = t & 15, ty = t >> 4;
    int r0 = ty*2, c0 = tx*4;
    float acc[2][4] = {};
    g24_2A(GR, TR, WA, WB, acc, r0, c0);
    __syncthreads();

    for (int i = t; i < 1024; i += 256) {
        *(float4*)(WA + i*4) = *(const float4*)(W1 + i*4);
        *(float4*)(WB + i*4) = *(const float4*)(W2 + i*4);
    }
#pragma unroll
    for (int i = 0; i < 2; i++) {
        int r = r0 + i;
        int id = ids[r];
        int p  = p0 + r;
        int l  = p % LL;
        float4 gv = *(float4*)(GR + r*64 + c0);
        float4 tv = *(float4*)(TR + r*64 + c0);
        float4 ev = *(const float4*)(emb + id*64 + c0);
        float4 pv = make_float4(0.f,0.f,0.f,0.f);
        if (id != 0) pv = *(const float4*)(posT + l*64 + c0);
        float s0 = tv.x + ev.x, s1 = tv.y + ev.y, s2 = tv.z + ev.z, s3 = tv.w + ev.w;
        float c0f = __fdividef(1.f, 1.f + __expf(-acc[i][0]));
        float c1f = __fdividef(1.f, 1.f + __expf(-acc[i][1]));
        float c2f = __fdividef(1.f, 1.f + __expf(-acc[i][2]));
        float c3f = __fdividef(1.f, 1.f + __expf(-acc[i][3]));
        s0 = fmaf(c0f, gv.x - tv.x, s0);
        s1 = fmaf(c1f, gv.y - tv.y, s1);
        s2 = fmaf(c2f, gv.z - tv.z, s2);
        s3 = fmaf(c3f, gv.w - tv.w, s3);
        *(float4*)(g_seqs + p*64 + c0) = make_float4(s0, s1, s2, s3);
        *(float4*)(GR + r*64 + c0) =
            make_float4(s0 + pv.x, s1 + pv.y, s2 + pv.z, s3 + pv.w);
    }
    __syncthreads();

    float m1[2][4] = {}, m2[2][4] = {};
    g24_2B(GR, WA, WB, m1, m2, r0, c0);
#pragma unroll
    for (int i = 0; i < 2; i++) {
        int p = p0 + r0 + i;
        *(float4*)(g_M1 + p*64 + c0) =
            make_float4(0.5f*m1[i][0], 0.5f*m1[i][1], 0.5f*m1[i][2], 0.5f*m1[i][3]);
        *(float4*)(g_M2 + p*64 + c0) =
            make_float4(0.5f*m2[i][0], 0.5f*m2[i][1], 0.5f*m2[i][2], 0.5f*m2[i][3]);
    }
}

// ============================================================
// K4a: score tiles — one block per causal 32x32 tile.
// ============================================================
__global__ __launch_bounds__(256) void k_score(const float* __restrict__ battn) {
    int b   = blockIdx.y;
    int tid = blockIdx.x;
    int qt = 0, base = 0;
    while (base + qt + 1 <= tid) { base += qt + 1; qt++; }
    int kt = tid - base;
    int t = threadIdx.x;

    __shared__ float m1s[32*68];
    __shared__ float m2s[32*64];
    __shared__ float bs2[64];

    for (int i = t; i < 512; i += 256) {
        int row = i >> 4, c4 = (i & 15)*4;
        int qg = qt*QT + row;
        float4 v = (qg < LL) ? *(const float4*)(g_M1 + (b*LL+qg)*64 + c4)
                             : make_float4(0.f,0.f,0.f,0.f);
        *(float4*)(m1s + row*68 + c4) = v;
        int kg = kt*KT + row;
        float4 w = (kg < LL) ? *(const float4*)(g_M2 + (b*LL+kg)*64 + c4)
                             : make_float4(0.f,0.f,0.f,0.f);
        *(float4*)(m2s + row*64 + c4) = w;
    }
    if (t < 64) bs2[t] = 0.5f * battn[t];
    __syncthreads();

    int ql = t & 31;
    int kb = (t >> 5) << 2;
    int qg = qt*QT + ql;

    float hs = 0.f;
#pragma unroll
    for (int d = 0; d < 64; d += 4) {
        float4 bv = *(float4*)(bs2 + d);
        hs += bv.x + bv.y + bv.z + bv.w;
    }

    float s0 = 0.f, s1 = 0.f, s2 = 0.f, s3 = 0.f;
#pragma unroll 4
    for (int d4 = 0; d4 < 64; d4 += 4) {
        float4 m1v = *(float4*)(m1s + ql*68 + d4);
        float4 b2  = *(float4*)(bs2 + d4);
        float4 k0  = *(float4*)(m2s + (kb+0)*64 + d4);
        float4 k1  = *(float4*)(m2s + (kb+1)*64 + d4);
        float4 k2  = *(float4*)(m2s + (kb+2)*64 + d4);
        float4 k3  = *(float4*)(m2s + (kb+3)*64 + d4);
        s0 = fmaf(b2.x, tanha(m1v.x + k0.x), s0);
        s1 = fmaf(b2.x, tanha(m1v.x + k1.x), s1);
        s2 = fmaf(b2.x, tanha(m1v.x + k2.x), s2);
        s3 = fmaf(b2.x, tanha(m1v.x + k3.x), s3);
        s0 = fmaf(b2.y, tanha(m1v.y + k0.y), s0);
        s1 = fmaf(b2.y, tanha(m1v.y + k1.y), s1);
        s2 = fmaf(b2.y, tanha(m1v.y + k2.y), s2);
        s3 = fmaf(b2.y, tanha(m1v.y + k3.y), s3);
        s0 = fmaf(b2.z, tanha(m1v.z + k0.z), s0);
        s1 = fmaf(b2.z, tanha(m1v.z + k1.z), s1);
        s2 = fmaf(b2.z, tanha(m1v.z + k2.z), s2);
        s3 = fmaf(b2.z, tanha(m1v.z + k3.z), s3);
        s0 = fmaf(b2.w, tanha(m1v.w + k0.w), s0);
        s1 = fmaf(b2.w, tanha(m1v.w + k1.w), s1);
        s2 = fmaf(b2.w, tanha(m1v.w + k2.w), s2);
        s3 = fmaf(b2.w, tanha(m1v.w + k3.w), s3);
    }
    if (qg < LL) {
        int kg0 = kt*KT + kb;
        float* srow = &g_score[((long long)b*LL + qg)*LL];
        if (kg0+0 < LL) srow[kg0+0] = (kg0+0 <= qg) ? s0 + hs : 0.f;
        if (kg0+1 < LL) srow[kg0+1] = (kg0+1 <= qg) ? s1 + hs : 0.f;
        if (kg0+2 < LL) srow[kg0+2] = (kg0+2 <= qg) ? s2 + hs : 0.f;
        if (kg0+3 < LL) srow[kg0+3] = (kg0+3 <= qg) ? s3 + hs : 0.f;
    }
}

// ============================================================
// K5 (balanced fused): block = (pair of q-tiles {6-2p, 5-2p}, b).
// ============================================================
__global__ __launch_bounds__(256) void k_ffn4(const int* __restrict__ pos_s,
                                              const int* __restrict__ neg_s,
                                              const float* __restrict__ emb,
                                              const float* __restrict__ c1w,
                                              const float* __restrict__ c1b,
                                              const float* __restrict__ c2w,
                                              const float* __restrict__ c2b,
                                              const float* __restrict__ upw,
                                              const float* __restrict__ upb,
                                              const float* __restrict__ gw,
                                              const float* __restrict__ gb,
                                              const float* __restrict__ dw,
                                              const float* __restrict__ db,
                                              float* __restrict__ out) {
    extern __shared__ float sm[];
    float* F0 = sm;
    float* R1 = sm + 4096;
    float* F2 = sm + 8192;
    float* WA = sm + 12288;
    float* WB = sm + 16384;
    float* GU = sm;
    float* seqss = WA;
    float* scsA  = WB;
    float* scsB  = WB + 1152;

    int t = threadIdx.x;
    int b = blockIdx.y;
    int p = blockIdx.x;
    int qtA = 6 - 2*p;
    int qtB = qtA - 1;

    int qrow  = t >> 3;
    int dbase = (t & 7) << 3;
    float accA[8], accB[8];
#pragma unroll
    for (int i = 0; i < 8; i++) { accA[i] = 0.f; accB[i] = 0.f; }

    for (int kt = 0; kt <= qtA; kt++) {
        __syncthreads();
        for (int i = t; i < 512; i += 256) {
            int kl = i >> 4, c4 = (i & 15) * 4;
            int kg = kt*KT + kl;
            float4 v = (kg < LL) ? *(const float4*)(g_seqs + (b*LL+kg)*64 + c4)
                                 : make_float4(0.f,0.f,0.f,0.f);
            *(float4*)(seqss + kl*64 + c4) = v;
        }
        {
            int ql = t >> 3, c4 = (t & 7) * 4;
            int kg = kt*KT + c4;
            int qgA = qtA*QT + ql;
            float4 v = (qgA < LL && kg < LL)
                     ? *(const float4*)(g_score + ((long long)b*LL + qgA)*LL + kg)
                     : make_float4(0.f,0.f,0.f,0.f);
            *(float4*)(scsA + ql*36 + c4) = v;
            float4 w = make_float4(0.f,0.f,0.f,0.f);
            if (qtB >= 0 && kg < LL) {
                int qgB = qtB*QT + ql;
                w = *(const float4*)(g_score + ((long long)b*LL + qgB)*LL + kg);
            }
            *(float4*)(scsB + ql*36 + c4) = w;
        }
        __syncthreads();
#pragma unroll 4
        for (int k = 0; k < KT; k++) {
            float svA = scsA[qrow*36 + k];
            float svB = scsB[qrow*36 + k];
            float4 v0 = *(float4*)(seqss + k*64 + dbase);
            float4 v1 = *(float4*)(seqss + k*64 + dbase + 4);
            accA[0] = fmaf(svA, v0.x, accA[0]);
            accA[1] = fmaf(svA, v0.y, accA[1]);
            accA[2] = fmaf(svA, v0.z, accA[2]);
            accA[3] = fmaf(svA, v0.w, accA[3]);
            accA[4] = fmaf(svA, v1.x, accA[4]);
            accA[5] = fmaf(svA, v1.y, accA[5]);
            accA[6] = fmaf(svA, v1.z, accA[6]);
            accA[7] = fmaf(svA, v1.w, accA[7]);
            accB[0] = fmaf(svB, v0.x, accB[0]);
            accB[1] = fmaf(svB, v0.y, accB[1]);
            accB[2] = fmaf(svB, v0.z, accB[2]);
            accB[3] = fmaf(svB, v0.w, accB[3]);
            accB[4] = fmaf(svB, v1.x, accB[4]);
            accB[5] = fmaf(svB, v1.y, accB[5]);
            accB[6] = fmaf(svB, v1.z, accB[6]);
            accB[7] = fmaf(svB, v1.w, accB[7]);
        }
    }
    __syncthreads();
    *(float4*)(F0 + qrow*64 + dbase)          = make_float4(accA[0], accA[1], accA[2], accA[3]);
    *(float4*)(F0 + qrow*64 + dbase + 4)      = make_float4(accA[4], accA[5], accA[6], accA[7]);
    *(float4*)(F0 + (32+qrow)*64 + dbase)     = make_float4(accB[0], accB[1], accB[2], accB[3]);
    *(float4*)(F0 + (32+qrow)*64 + dbase + 4) = make_float4(accB[4], accB[5], accB[6], accB[7]);
    __syncthreads();

    int tx = t & 15, ty = t >> 4;
    int r0 = ty*4, c0 = tx*4;

    for (int i = t; i < 1024; i += 256) {
        *(float4*)(WA + i*4) = *(const float4*)(c1w + i*4);
        *(float4*)(WB + i*4) = *(const float4*)(c2w + i*4);
    }
    __syncthreads();

    {
        float a2[4][4] = {};
        gemm_acc(F0, WA, a2, r0, c0);
        float4 bv = *(const float4*)(c1b + c0);
#pragma unroll
        for (int i = 0; i < 4; i++)
            *(float4*)(R1 + (r0+i)*64 + c0) = make_float4(
                fmaxf(a2[i][0] + bv.x, 0.f), fmaxf(a2[i][1] + bv.y, 0.f),
                fmaxf(a2[i][2] + bv.z, 0.f), fmaxf(a2[i][3] + bv.w, 0.f));
    }
    __syncthreads();

    {
        float a2[4][4] = {};
        gemm_acc(R1, WB, a2, r0, c0);
        float4 bv = *(const float4*)(c2b + c0);
#pragma unroll
        for (int i = 0; i < 4; i++) {
            float4 f0v = *(float4*)(F0 + (r0+i)*64 + c0);
            *(float4*)(F2 + (r0+i)*64 + c0) = make_float4(
                f0v.x + a2[i][0] + bv.x, f0v.y + a2[i][1] + bv.y,
                f0v.z + a2[i][2] + bv.z, f0v.w + a2[i][3] + bv.w);
        }
    }
    __syncthreads();

#pragma unroll
    for (int half = 0; half < 2; half++) {
        for (int i = t; i < 1024; i += 256) {
            int row = i >> 4, c4 = (i & 15) * 4;
            *(float4*)(WA + row*64 + c4) = *(const float4*)(upw + row*128 + half*64 + c4);
            *(float4*)(WB + row*64 + c4) = *(const float4*)(gw  + row*128 + half*64 + c4);
        }
        __syncthreads();
        float au[4][4] = {}, ag[4][4] = {};
        gemm_acc2B4(F2, WA, WB, au, ag, r0, c0);
        float4 ub  = *(const float4*)(upb + half*64 + c0);
        float4 gb4 = *(const float4*)(gb + half*64 + c0);
#pragma unroll
        for (int i = 0; i < 4; i++) {
            float g0v = fmaxf(ag[i][0] + gb4.x, 0.f) * (au[i][0] + ub.x);
            float g1v = fmaxf(ag[i][1] + gb4.y, 0.f) * (au[i][1] + ub.y);
            float g2v = fmaxf(ag[i][2] + gb4.z, 0.f) * (au[i][2] + ub.z);
            float g3v = fmaxf(ag[i][3] + gb4.w, 0.f) * (au[i][3] + ub.w);
            *(float4*)(GU + (r0+i)*128 + half*64 + c0) = make_float4(g0v, g1v, g2v, g3v);
        }
        __syncthreads();
    }

    for (int i = t; i < 1024; i += 256) {
        *(float4*)(WA + i*4) = *(const float4*)(dw + i*4);
        *(float4*)(WB + i*4) = *(const float4*)(dw + 4096 + i*4);
    }
    __syncthreads();
    float fo[4][4];
    {
        float a2[4][4] = {};
#pragma unroll 4
        for (int k4 = 0; k4 < 128; k4 += 4) {
            const float* Bsrc = (k4 < 64) ? (WA + k4*64) : (WB + (k4-64)*64);
            float aa[4][4], bb[4][4];
#pragma unroll
            for (int i = 0; i < 4; i++)
                *(float4*)aa[i] = *(const float4*)(GU + (r0+i)*128 + k4);
#pragma unroll
            for (int kk = 0; kk < 4; kk++)
                *(float4*)bb[kk] = *(const float4*)(Bsrc + kk*64 + c0);
#pragma unroll
            for (int kk = 0; kk < 4; kk++)
#pragma unroll
                for (int i = 0; i < 4; i++)
#pragma unroll
                    for (int j = 0; j < 4; j++)
                        a2[i][j] = fmaf(aa[i][kk], bb[kk][j], a2[i][j]);
        }
        float4 bv = *(const float4*)(db + c0);
#pragma unroll
        for (int i = 0; i < 4; i++) {
            float4 f2v = *(float4*)(F2 + (r0+i)*64 + c0);
            fo[i][0] = f2v.x + fmaxf(a2[i][0] + bv.x, 0.f);
            fo[i][1] = f2v.y + fmaxf(a2[i][1] + bv.y, 0.f);
            fo[i][2] = f2v.z + fmaxf(a2[i][2] + bv.z, 0.f);
            fo[i][3] = f2v.w + fmaxf(a2[i][3] + bv.w, 0.f);
        }
    }
    __syncthreads();
#pragma unroll
    for (int i = 0; i < 4; i++)
        *(float4*)(WA + (r0+i)*64 + c0) =
            make_float4(fo[i][0], fo[i][1], fo[i][2], fo[i][3]);
    __syncthreads();

    {
        int r  = t >> 2;
        int q  = t & 3;
        int d0 = q * 16;
        int qg = (r < 32) ? (qtA*QT + r)
                          : ((qtB >= 0) ? (qtB*QT + r - 32) : LL);
        if (qg < LL) {
            int gp = b*LL + qg;
            int ip = pos_s[gp], in_ = neg_s[gp];
            float pl = 0.f, nl = 0.f;
#pragma unroll
            for (int d = 0; d < 16; d += 4) {
                float4 f  = *(float4*)(WA + r*64 + d0 + d);
                float4 ep = *(const float4*)(emb + ip*64 + d0 + d);
                float4 en = *(const float4*)(emb + in_*64 + d0 + d);
                pl += f.x*ep.x + f.y*ep.y + f.z*ep.z + f.w*ep.w;
                nl += f.x*en.x + f.y*en.y + f.z*en.z + f.w*en.w;
            }
            pl += __shfl_xor_sync(0xffffffffu, pl, 1);
            pl += __shfl_xor_sync(0xffffffffu, pl, 2);
            nl += __shfl_xor_sync(0xffffffffu, nl, 1);
            nl += __shfl_xor_sync(0xffffffffu, nl, 2);
            if (q == 0) { out[gp] = pl; out[NP + gp] = nl; }
        }
    }
}

// ============================================================
extern "C" void kernel_launch(void* const* d_in, const int* in_sizes, int n_in,
                              void* d_out, int out_size) {
    const int*   log_seqs = (const int*)  d_in[0];
    const int*   pos_seqs = (const int*)  d_in[1];
    const int*   neg_seqs = (const int*)  d_in[2];
    const float* adj      = (const float*)d_in[4];
    const float* item_emb = (const float*)d_in[5];
    const float* pos_emb  = (const float*)d_in[6];
    const float* W_item   = (const float*)d_in[7];
    const float* a_item   = (const float*)d_in[8];
    const float* W_1      = (const float*)d_in[9];
    const float* W_2      = (const float*)d_in[10];
    const float* b_attn   = (const float*)d_in[11];
    const float* co_c     = (const float*)d_in[12];
    const float* co_n     = (const float*)d_in[13];
    const float* c1w      = (const float*)d_in[14];
    const float* c1b      = (const float*)d_in[15];
    const float* c2w      = (const float*)d_in[16];
    const float* c2b      = (const float*)d_in[17];
    const float* upw      = (const float*)d_in[18];
    const float* upb      = (const float*)d_in[19];
    const float* gw       = (const float*)d_in[20];
    const float* gb       = (const float*)d_in[21];
    const float* dw       = (const float*)d_in[22];
    const float* db       = (const float*)d_in[23];
    float* out = (float*)d_out;

    static bool attr_done = false;
    if (!attr_done) {
        cudaFuncSetAttribute(k_seq2, cudaFuncAttributeMaxDynamicSharedMemorySize, 49152);
        cudaFuncSetAttribute(k_ffn4, cudaFuncAttributeMaxDynamicSharedMemorySize, 81920);
        attr_done = true;
    }

    k_zero <<<(NI + 255) / 256, 256>>>();
    k_mark <<<(NP + 255) / 256, 256>>>(log_seqs);
    k_h2   <<<(NI + 63) / 64, 256>>>(item_emb, W_item, a_item);
    k_adjf <<<(NI + 7) / 8, 256>>>(adj);
    k_seq2 <<<NP / 32, 256, 49152>>>(log_seqs, item_emb, pos_emb,
                                     co_c, co_n, W_1, W_2);
    dim3 sg(28, BB);
    k_score<<<sg, 256>>>(b_attn);
    dim3 fg(4, BB);
    k_ffn4 <<<fg, 256, 81920>>>(pos_seqs, neg_seqs, item_emb,
                                c1w, c1b, c2w, c2b, upw, upb,
                                gw, gb, dw, db, out);
}